// round 13
// baseline (speedup 1.0000x reference)
#include <cuda_runtime.h>
#include <math.h>

#define TT 512
#define DD 512
#define NBATCH 2
#define VV 256
#define MMEM 256
#define BT 1024
#define D3 1536
#define HALF_BLOCKS 64
#define UNITS 8
#define GRU_THREADS 512

// ---------------- static device scratch ----------------
__device__ float g_table[VV * D3];
__device__ float g_pf[BT * DD];
__device__ float g_ps[BT * DD];
__device__ float g_qkv[BT * D3];
__device__ float g_S[NBATCH * TT * TT];
__device__ float g_attn[BT * MMEM];
__device__ float g_comb[BT * 2048];
__device__ float g_tpre[BT * DD];
__device__ float g_gatepre[BT * DD];
__device__ float g_qh[BT * DD];
__device__ float g_sw[VV * DD];
__device__ float g_hf3[3][NBATCH * DD];
__device__ float g_hs3[3][NBATCH * DD];
__device__ unsigned g_barf;
__device__ unsigned g_bars;

// ---------------- block reductions ----------------
__device__ __forceinline__ float block_red_sum(float v, float* sb) {
    __syncthreads();
    int lane = threadIdx.x & 31, w = threadIdx.x >> 5;
    #pragma unroll
    for (int o = 16; o; o >>= 1) v += __shfl_xor_sync(0xffffffffu, v, o);
    if (lane == 0) sb[w] = v;
    __syncthreads();
    float r = (lane < (int)(blockDim.x >> 5)) ? sb[lane] : 0.f;
    #pragma unroll
    for (int o = 16; o; o >>= 1) r += __shfl_xor_sync(0xffffffffu, r, o);
    return r;
}

__device__ __forceinline__ float block_red_max(float v, float* sb) {
    __syncthreads();
    int lane = threadIdx.x & 31, w = threadIdx.x >> 5;
    #pragma unroll
    for (int o = 16; o; o >>= 1) v = fmaxf(v, __shfl_xor_sync(0xffffffffu, v, o));
    if (lane == 0) sb[w] = v;
    __syncthreads();
    float r = (lane < (int)(blockDim.x >> 5)) ? sb[lane] : -3.4e38f;
    #pragma unroll
    for (int o = 16; o; o >>= 1) r = fmaxf(r, __shfl_xor_sync(0xffffffffu, r, o));
    return r;
}

__global__ void reset_bar_kernel() { g_barf = 0u; g_bars = 0u; }

// ---------------- fast activations ----------------
__device__ __forceinline__ float sigf(float x) {
    return __fdividef(1.f, 1.f + __expf(-x));
}
__device__ __forceinline__ float tanhf_fast(float x) {
    float ax = fabsf(x);
    float t = __expf(-2.f * ax);
    float r = __fdividef(1.f - t, 1.f + t);
    return copysignf(r, x);
}

#define FMA2(d, a, b, c) \
    asm("fma.rn.f32x2 %0, %1, %2, %3;" : "=l"(d) : "l"(a), "l"(b), "l"(c))

__device__ __forceinline__ void red_rel(unsigned* p) {
    asm volatile("red.release.gpu.global.add.u32 [%0], 1;" :: "l"(p) : "memory");
}
__device__ __forceinline__ void poll_ge(unsigned* p, unsigned target) {
    unsigned v;
    do {
        asm volatile("ld.acquire.gpu.u32 %0, [%1];" : "=r"(v) : "l"(p) : "memory");
    } while (v < target);
}

// ---------------- split-domain GRU ----------------
// blocks 0..63  : FAST domain (8 units, warps 0-7 dots on fast_whh, barrier g_barf)
// blocks 64..127: SLOW domain (8 units, 16 warps: tr0=slow_wih on pf[t], tr1=slow_whh;
//                 barrier g_bars; waits on g_barf for pf[t] availability)
__global__ void __launch_bounds__(GRU_THREADS) fused_gru_kernel(
    const float* __restrict__ fast_whh, const float* __restrict__ fast_bhh,
    const float* __restrict__ slow_wih, const float* __restrict__ slow_bih,
    const float* __restrict__ slow_whh, const float* __restrict__ slow_bhh,
    const float* __restrict__ gi_table, const int* __restrict__ toks,
    const float* __restrict__ hf0, const float* __restrict__ hs0,
    float* __restrict__ pf, float* __restrict__ comb, float* __restrict__ ps,
    float* __restrict__ hfT, float* __restrict__ hsT)
{
    __shared__ float sgf[3][NBATCH][UNITS];         // fast: [gate][batch][unit]
    __shared__ float sgs[2][3][NBATCH][UNITS];      // slow: [trio][gate][batch][unit]
    const int tid = threadIdx.x;
    const int w = tid >> 5, lane = tid & 31;
    const bool isfast = blockIdx.x < HALF_BLOCKS;
    const int ibase = (isfast ? blockIdx.x : blockIdx.x - HALF_BLOCKS) * UNITS;

    int il = 0, tr = 0;
    bool working;
    ulonglong2 wreg[3][4];
    if (isfast) {
        working = (w < 8);
        il = w & 7;
        if (working) {
            const int i = ibase + il;
            #pragma unroll
            for (int g = 0; g < 3; g++)
                #pragma unroll
                for (int j = 0; j < 4; j++)
                    wreg[g][j] = *(const ulonglong2*)&fast_whh[(size_t)(g * DD + i) * DD + lane * 4 + j * 128];
        }
    } else {
        working = true;
        tr = w >> 3; il = w & 7;
        const int i = ibase + il;
        const float* Wsrc = tr ? slow_whh : slow_wih;
        #pragma unroll
        for (int g = 0; g < 3; g++)
            #pragma unroll
            for (int j = 0; j < 4; j++)
                wreg[g][j] = *(const ulonglong2*)&Wsrc[(size_t)(g * DD + i) * DD + lane * 4 + j * 128];
    }

    // cells: warp 0 lanes 0..15 (8 units x 2 batches)
    const int cb = lane >> 3, cil = lane & 7;
    const int ci = ibase + cil;
    float b_r = 0.f, b_z = 0.f, b_n = 0.f;       // fast bhh / slow bih
    float b2_r = 0.f, b2_z = 0.f, b2_n = 0.f;    // slow bhh
    float hprev = 0.f;
    if (w == 0 && lane < 16) {
        if (isfast) {
            b_r = fast_bhh[ci]; b_z = fast_bhh[DD + ci]; b_n = fast_bhh[2 * DD + ci];
            hprev = hf0[cb * DD + ci];
            g_hf3[0][cb * DD + ci] = hprev;
        } else {
            b_r = slow_bih[ci]; b_z = slow_bih[DD + ci]; b_n = slow_bih[2 * DD + ci];
            b2_r = slow_bhh[ci]; b2_z = slow_bhh[DD + ci]; b2_n = slow_bhh[2 * DD + ci];
            hprev = hs0[cb * DD + ci];
            g_hs3[0][cb * DD + ci] = hprev;
        }
    }
    __syncthreads();
    if (tid == 0) {
        if (isfast) { red_rel(&g_barf); poll_ge(&g_barf, HALF_BLOCKS); }
        else {
            red_rel(&g_bars);
            poll_ge(&g_bars, HALF_BLOCKS);
            poll_ge(&g_barf, 2 * HALF_BLOCKS);    // pf[0] ready
        }
    }
    __syncthreads();

    for (int t = 0; t < TT; t++) {
        const int cur = t % 3, nxt = (t + 1) % 3;

        // fast-cell gi prefetch
        float gr = 0.f, gz = 0.f, gn = 0.f;
        if (isfast && w == 0 && lane < 16) {
            const int row = cb * TT + t;
            const float* gi = gi_table + (size_t)__ldg(&toks[row]) * D3;
            gr = __ldg(gi + ci); gz = __ldg(gi + DD + ci); gn = __ldg(gi + 2 * DD + ci);
        }

        if (working) {
            ulonglong2 xv[NBATCH][4];
            if (isfast) {
                #pragma unroll
                for (int b = 0; b < NBATCH; b++)
                    #pragma unroll
                    for (int j = 0; j < 4; j++)
                        xv[b][j] = __ldcg((const ulonglong2*)&g_hf3[cur][b * DD + lane * 4 + j * 128]);
            } else if (tr == 0) {
                #pragma unroll
                for (int b = 0; b < NBATCH; b++) {
                    const float* pfb = pf + (size_t)(b * TT + t) * DD;
                    #pragma unroll
                    for (int j = 0; j < 4; j++)
                        xv[b][j] = __ldcg((const ulonglong2*)(pfb + lane * 4 + j * 128));
                }
            } else {
                #pragma unroll
                for (int b = 0; b < NBATCH; b++)
                    #pragma unroll
                    for (int j = 0; j < 4; j++)
                        xv[b][j] = __ldcg((const ulonglong2*)&g_hs3[cur][b * DD + lane * 4 + j * 128]);
            }

            unsigned long long acc2[3][NBATCH];
            #pragma unroll
            for (int g = 0; g < 3; g++)
                #pragma unroll
                for (int b = 0; b < NBATCH; b++) acc2[g][b] = 0ull;
            #pragma unroll
            for (int j = 0; j < 4; j++)
                #pragma unroll
                for (int g = 0; g < 3; g++)
                    #pragma unroll
                    for (int b = 0; b < NBATCH; b++) {
                        FMA2(acc2[g][b], wreg[g][j].x, xv[b][j].x, acc2[g][b]);
                        FMA2(acc2[g][b], wreg[g][j].y, xv[b][j].y, acc2[g][b]);
                    }

            float a[3][NBATCH];
            #pragma unroll
            for (int g = 0; g < 3; g++)
                #pragma unroll
                for (int b = 0; b < NBATCH; b++) {
                    float lo, hi;
                    asm("mov.b64 {%0, %1}, %2;" : "=f"(lo), "=f"(hi) : "l"(acc2[g][b]));
                    a[g][b] = lo + hi;
                }
            #pragma unroll
            for (int o = 16; o; o >>= 1)
                #pragma unroll
                for (int g = 0; g < 3; g++)
                    #pragma unroll
                    for (int b = 0; b < NBATCH; b++)
                        a[g][b] += __shfl_xor_sync(0xffffffffu, a[g][b], o);

            if (lane == 0) {
                #pragma unroll
                for (int g = 0; g < 3; g++)
                    #pragma unroll
                    for (int b = 0; b < NBATCH; b++) {
                        if (isfast) sgf[g][b][il] = a[g][b];
                        else        sgs[tr][g][b][il] = a[g][b];
                    }
            }
        }
        __syncthreads();

        if (w == 0 && lane < 16) {
            if (isfast) {                           // fast GRU step t
                const int row = cb * TT + t;
                float r = sigf(gr + sgf[0][cb][cil] + b_r);
                float z = sigf(gz + sgf[1][cb][cil] + b_z);
                float n = tanhf_fast(gn + r * (sgf[2][cb][cil] + b_n));
                float hnew = (1.f - z) * n + z * hprev;
                hprev = hnew;
                g_hf3[nxt][cb * DD + ci] = hnew;
                pf[(size_t)row * DD + ci] = hnew;
                comb[(size_t)row * 2048 + ci] = hnew;
                if (t == TT - 1) hfT[cb * DD + ci] = hnew;
            } else {                                // slow GRU step t
                const int row = cb * TT + t;
                float r = sigf(sgs[0][0][cb][cil] + b_r + sgs[1][0][cb][cil] + b2_r);
                float z = sigf(sgs[0][1][cb][cil] + b_z + sgs[1][1][cb][cil] + b2_z);
                float n = tanhf_fast(sgs[0][2][cb][cil] + b_n + r * (sgs[1][2][cb][cil] + b2_n));
                float hnew = (1.f - z) * n + z * hprev;
                hprev = hnew;
                g_hs3[nxt][cb * DD + ci] = hnew;
                ps[(size_t)row * DD + ci] = hnew;
                if (t == TT - 1) hsT[cb * DD + ci] = hnew;
            }
        }
        __syncthreads();
        if (tid == 0) {
            if (isfast) {
                red_rel(&g_barf);                   // publish pf[t] / hf state
                if (t < TT - 1) poll_ge(&g_barf, (unsigned)(t + 2) * HALF_BLOCKS);
            } else if (t < TT - 1) {
                red_rel(&g_bars);
                poll_ge(&g_bars, (unsigned)(t + 2) * HALF_BLOCKS);
                poll_ge(&g_barf, (unsigned)(t + 3) * HALF_BLOCKS);  // pf[t+1]
            }
        }
        __syncthreads();
    }
}

// ---------------- GEMM: 128x64 tile, 256 thr, 8x4/thread, f32x2 FMA ----------------
// TB=true : Bm stored [N,K]  (C = A @ Bm^T);  TB=false: Bm stored [K,N]
// CAUSAL: zero where col > row; fully-masked tiles skip the K loop.
// klim != 0: cap K at m0+128 (for S@v where S is lower-triangular).
// elu_cols: apply elu(x)+1 to output columns < elu_cols.
template <bool TB, bool CAUSAL>
__global__ void __launch_bounds__(256) gemm_kernel(
    const float* __restrict__ A, const float* __restrict__ Bm,
    const float* __restrict__ bias, float* __restrict__ C,
    int M, int N, int K, int lda, int ldb, int ldc,
    long long sA, long long sB, long long sC, float scale,
    int klim, int elu_cols)
{
    __shared__ __align__(16) float As[2][16][132];
    __shared__ __align__(16) float Bs[2][16][68];
    const int z = blockIdx.z;
    A += (size_t)z * sA; Bm += (size_t)z * sB; C += (size_t)z * sC;
    const int m0 = blockIdx.y * 128, n0 = blockIdx.x * 64;
    const int tid = threadIdx.x;
    const int ty = tid >> 4, tx = tid & 15;
    const int nn = n0 + (tx << 2);

    if (CAUSAL && n0 > m0 + 127) {
        float4 zv = make_float4(0.f, 0.f, 0.f, 0.f);
        #pragma unroll
        for (int p2 = 0; p2 < 4; p2++)
            #pragma unroll
            for (int half = 0; half < 2; half++) {
                const int mm = m0 + (ty << 3) + (p2 << 1) + half;
                *(float4*)(C + (size_t)mm * ldc + nn) = zv;
            }
        return;
    }

    const int Kc = klim ? ((m0 + 128 < K) ? m0 + 128 : K) : K;
    const int ar = tid >> 2, ac = (tid & 3) << 2;
    const int bk = tid >> 4, bn = (tid & 15) << 2;

    float4 a0 = *(const float4*)(A + (size_t)(m0 + ar) * lda + ac);
    float4 a1 = *(const float4*)(A + (size_t)(m0 + ar + 64) * lda + ac);
    float4 bv;
    if (TB) bv = *(const float4*)(Bm + (size_t)(n0 + ar) * ldb + ac);
    else    bv = *(const float4*)(Bm + (size_t)bk * ldb + n0 + bn);

    {
        As[0][ac + 0][ar] = a0.x; As[0][ac + 1][ar] = a0.y;
        As[0][ac + 2][ar] = a0.z; As[0][ac + 3][ar] = a0.w;
        As[0][ac + 0][ar + 64] = a1.x; As[0][ac + 1][ar + 64] = a1.y;
        As[0][ac + 2][ar + 64] = a1.z; As[0][ac + 3][ar + 64] = a1.w;
        if (TB) {
            Bs[0][ac + 0][ar] = bv.x; Bs[0][ac + 1][ar] = bv.y;
            Bs[0][ac + 2][ar] = bv.z; Bs[0][ac + 3][ar] = bv.w;
        } else {
            *(float4*)&Bs[0][bk][bn] = bv;
        }
    }
    __syncthreads();

    unsigned long long acc[4][4];
    #pragma unroll
    for (int p2 = 0; p2 < 4; p2++)
        #pragma unroll
        for (int jj = 0; jj < 4; jj++) acc[p2][jj] = 0ull;

    const int P = Kc >> 4;
    int buf = 0;
    for (int p = 0; p < P; p++) {
        if (p + 1 < P) {
            const int k0n = (p + 1) << 4;
            a0 = *(const float4*)(A + (size_t)(m0 + ar) * lda + k0n + ac);
            a1 = *(const float4*)(A + (size_t)(m0 + ar + 64) * lda + k0n + ac);
            if (TB) bv = *(const float4*)(Bm + (size_t)(n0 + ar) * ldb + k0n + ac);
            else    bv = *(const float4*)(Bm + (size_t)(k0n + bk) * ldb + n0 + bn);
        }
        #pragma unroll
        for (int k = 0; k < 16; k++) {
            ulonglong2 alo = *(const ulonglong2*)&As[buf][k][ty << 3];
            ulonglong2 ahi = *(const ulonglong2*)&As[buf][k][(ty << 3) + 4];
            float4 b4 = *(const float4*)&Bs[buf][k][tx << 2];
            unsigned long long bd[4];
            asm("mov.b64 %0, {%1, %1};" : "=l"(bd[0]) : "f"(b4.x));
            asm("mov.b64 %0, {%1, %1};" : "=l"(bd[1]) : "f"(b4.y));
            asm("mov.b64 %0, {%1, %1};" : "=l"(bd[2]) : "f"(b4.z));
            asm("mov.b64 %0, {%1, %1};" : "=l"(bd[3]) : "f"(b4.w));
            #pragma unroll
            for (int jj = 0; jj < 4; jj++) {
                FMA2(acc[0][jj], alo.x, bd[jj], acc[0][jj]);
                FMA2(acc[1][jj], alo.y, bd[jj], acc[1][jj]);
                FMA2(acc[2][jj], ahi.x, bd[jj], acc[2][jj]);
                FMA2(acc[3][jj], ahi.y, bd[jj], acc[3][jj]);
            }
        }
        if (p + 1 < P) {
            const int nb = buf ^ 1;
            As[nb][ac + 0][ar] = a0.x; As[nb][ac + 1][ar] = a0.y;
            As[nb][ac + 2][ar] = a0.z; As[nb][ac + 3][ar] = a0.w;
            As[nb][ac + 0][ar + 64] = a1.x; As[nb][ac + 1][ar + 64] = a1.y;
            As[nb][ac + 2][ar + 64] = a1.z; As[nb][ac + 3][ar + 64] = a1.w;
            if (TB) {
                Bs[nb][ac + 0][ar] = bv.x; Bs[nb][ac + 1][ar] = bv.y;
                Bs[nb][ac + 2][ar] = bv.z; Bs[nb][ac + 3][ar] = bv.w;
            } else {
                *(float4*)&Bs[nb][bk][bn] = bv;
            }
            __syncthreads();
            buf = nb;
        }
    }

    float4 bvec;
    if (bias) bvec = *(const float4*)&bias[nn];
    #pragma unroll
    for (int p2 = 0; p2 < 4; p2++) {
        float rlo[4], rhi[4];
        #pragma unroll
        for (int jj = 0; jj < 4; jj++) {
            float lo, hi;
            asm("mov.b64 {%0, %1}, %2;" : "=f"(lo), "=f"(hi) : "l"(acc[p2][jj]));
            rlo[jj] = lo; rhi[jj] = hi;
        }
        #pragma unroll
        for (int half = 0; half < 2; half++) {
            const int mm = m0 + (ty << 3) + (p2 << 1) + half;
            float* rr = half ? rhi : rlo;
            float4 cv;
            cv.x = rr[0] * scale; cv.y = rr[1] * scale;
            cv.z = rr[2] * scale; cv.w = rr[3] * scale;
            if (bias) { cv.x += bvec.x; cv.y += bvec.y; cv.z += bvec.z; cv.w += bvec.w; }
            if (elu_cols) {
                if (nn + 0 < elu_cols) cv.x = cv.x > 0.f ? cv.x + 1.f : __expf(cv.x);
                if (nn + 1 < elu_cols) cv.y = cv.y > 0.f ? cv.y + 1.f : __expf(cv.y);
                if (nn + 2 < elu_cols) cv.z = cv.z > 0.f ? cv.z + 1.f : __expf(cv.z);
                if (nn + 3 < elu_cols) cv.w = cv.w > 0.f ? cv.w + 1.f : __expf(cv.w);
            }
            if (CAUSAL) {
                if (nn + 0 > mm) cv.x = 0.f;
                if (nn + 1 > mm) cv.y = 0.f;
                if (nn + 2 > mm) cv.z = 0.f;
                if (nn + 3 > mm) cv.w = 0.f;
            }
            *(float4*)(C + (size_t)mm * ldc + nn) = cv;
        }
    }
}

// ---------------- small kernels ----------------
__global__ void den_div_kernel() {
    __shared__ float sb[32];
    int row = blockIdx.x;
    float s = 0.f;
    for (int c = threadIdx.x; c < TT; c += 256) s += g_S[(size_t)row * TT + c];
    s = block_red_sum(s, sb);
    float inv = __fdividef(1.f, s + 1e-6f);
    for (int j = threadIdx.x; j < DD; j += 256)
        g_comb[(size_t)row * 2048 + 1024 + j] *= inv;
}

__global__ void softmax_kernel() {
    __shared__ float sb[32];
    int row = blockIdx.x;
    float x = g_attn[(size_t)row * MMEM + threadIdx.x];
    float m = block_red_max(x, sb);
    float e = __expf(x - m);
    float s = block_red_sum(e, sb);
    g_attn[(size_t)row * MMEM + threadIdx.x] = e / s;
}

__device__ __forceinline__ float tanh_bulk(float x) {
    float ax = fabsf(x);
    float t = __expf(-2.f * ax);
    float r = __fdividef(1.f - t, 1.f + t);
    return copysignf(r, x);
}

// mode 0: out = tanh(LN(in));  mode 1: out = LN(tanh(in))
__global__ void ln_kernel(const float* __restrict__ in, const float* __restrict__ gg,
                          const float* __restrict__ bb, float* __restrict__ out,
                          int ldo, int mode)
{
    __shared__ float sb[32];
    int row = blockIdx.x, tid = threadIdx.x;
    float x0 = in[(size_t)row * DD + tid];
    float x1 = in[(size_t)row * DD + 256 + tid];
    if (mode == 1) { x0 = tanh_bulk(x0); x1 = tanh_bulk(x1); }
    float s  = block_red_sum(x0 + x1, sb);
    float sq = block_red_sum(x0 * x0 + x1 * x1, sb);
    float mean = s * (1.f / 512.f);
    float var  = sq * (1.f / 512.f) - mean * mean;
    float rstd = rsqrtf(var + 1e-5f);
    float y0 = (x0 - mean) * rstd * gg[tid] + bb[tid];
    float y1 = (x1 - mean) * rstd * gg[256 + tid] + bb[256 + tid];
    if (mode == 0) { y0 = tanh_bulk(y0); y1 = tanh_bulk(y1); }
    out[(size_t)row * ldo + tid] = y0;
    out[(size_t)row * ldo + 256 + tid] = y1;
}

__global__ void rownorm_kernel(const float* __restrict__ src) {
    __shared__ float sb[32];
    int row = blockIdx.x, tid = threadIdx.x;
    float x0 = src[(size_t)row * DD + tid];
    float x1 = src[(size_t)row * DD + 256 + tid];
    float ss = block_red_sum(x0 * x0 + x1 * x1, sb);
    float inv = 1.f / fmaxf(sqrtf(ss), 1e-12f);
    g_sw[(size_t)row * DD + tid] = x0 * inv;
    g_sw[(size_t)row * DD + 256 + tid] = x1 * inv;
}

// ---------------- host ----------------
static inline void gemm(const float* A, const float* B, const float* bias, float* C,
                        int M, int N, int K, int lda, int ldb, int ldc,
                        float scale, int batch, long long sA, long long sB, long long sC,
                        bool tb, bool causal, int klim = 0, int elu_cols = 0)
{
    dim3 grid(N / 64, M / 128, batch);
    if (tb) {
        if (causal)
            gemm_kernel<true, true><<<grid, 256>>>(A, B, bias, C, M, N, K, lda, ldb, ldc, sA, sB, sC, scale, klim, elu_cols);
        else
            gemm_kernel<true, false><<<grid, 256>>>(A, B, bias, C, M, N, K, lda, ldb, ldc, sA, sB, sC, scale, klim, elu_cols);
    } else {
        gemm_kernel<false, false><<<grid, 256>>>(A, B, bias, C, M, N, K, lda, ldb, ldc, sA, sB, sC, scale, klim, elu_cols);
    }
}

extern "C" void kernel_launch(void* const* d_in, const int* in_sizes, int n_in,
                              void* d_out, int out_size)
{
    (void)in_sizes; (void)n_in; (void)out_size;
    const int*   x        = (const int*)d_in[0];
    const float* h_f      = (const float*)d_in[1];
    const float* h_s      = (const float*)d_in[2];
    const float* soma_w   = (const float*)d_in[3];
    const float* fast_wih = (const float*)d_in[4];
    const float* fast_whh = (const float*)d_in[5];
    const float* fast_bih = (const float*)d_in[6];
    const float* fast_bhh = (const float*)d_in[7];
    const float* slow_wih = (const float*)d_in[8];
    const float* slow_whh = (const float*)d_in[9];
    const float* slow_bih = (const float*)d_in[10];
    const float* slow_bhh = (const float*)d_in[11];
    const float* qkv_w    = (const float*)d_in[12];
    const float* qkv_b    = (const float*)d_in[13];
    const float* gate_w   = (const float*)d_in[14];
    const float* gate_b   = (const float*)d_in[15];
    const float* gate_g   = (const float*)d_in[16];
    const float* gate_bb  = (const float*)d_in[17];
    const float* mem_bank = (const float*)d_in[18];
    const float* hip_qw   = (const float*)d_in[19];
    const float* hip_qb   = (const float*)d_in[20];
    const float* axon_w   = (const float*)d_in[21];
    const float* axon_b   = (const float*)d_in[22];
    const float* norm_g   = (const float*)d_in[23];
    const float* norm_b   = (const float*)d_in[24];

    float* out = (float*)d_out;
    float* out_logits  = out;            // [B,T,V]
    float* out_thought = out + 262144;   // [B,T,D]
    float* out_hf      = out + 786432;   // [1,B,D]
    float* out_hs      = out + 787456;   // [1,B,D]

    float *p_table, *p_pf, *p_ps, *p_qkv, *p_S, *p_attn, *p_comb,
          *p_tpre, *p_gatepre, *p_qh, *p_sw;
    cudaGetSymbolAddress((void**)&p_table,   g_table);
    cudaGetSymbolAddress((void**)&p_pf,      g_pf);
    cudaGetSymbolAddress((void**)&p_ps,      g_ps);
    cudaGetSymbolAddress((void**)&p_qkv,     g_qkv);
    cudaGetSymbolAddress((void**)&p_S,       g_S);
    cudaGetSymbolAddress((void**)&p_attn,    g_attn);
    cudaGetSymbolAddress((void**)&p_comb,    g_comb);
    cudaGetSymbolAddress((void**)&p_tpre,    g_tpre);
    cudaGetSymbolAddress((void**)&p_gatepre, g_gatepre);
    cudaGetSymbolAddress((void**)&p_qh,      g_qh);
    cudaGetSymbolAddress((void**)&p_sw,      g_sw);

    // normalized embedding rows for logits
    rownorm_kernel<<<VV, 256>>>(soma_w);

    // fast-GRU input-gate token table: [V,3D] = soma_w @ fast_wih^T + fast_bih
    gemm(soma_w, fast_wih, fast_bih, p_table, 256, 1536, 512, 512, 512, 1536,
         1.f, 1, 0, 0, 0, true, false);

    // reset counters BEFORE the GRU (keeps fused_gru in the ncu window)
    reset_bar_kernel<<<1, 1>>>();

    // split-domain GRUs -> p_f, comb[:,0:512], p_s, hf1, hs1
    fused_gru_kernel<<<2 * HALF_BLOCKS, GRU_THREADS>>>(
        fast_whh, fast_bhh, slow_wih, slow_bih, slow_whh, slow_bhh,
        p_table, x, h_f, h_s, p_pf, p_comb, p_ps, out_hf, out_hs);

    // projections from p_s (elu fused into qkv epilogue for q,k cols)
    gemm(p_ps, qkv_w,  qkv_b,  p_qkv,     1024, 1536, 512, 512, 512, 1536, 1.f, 1, 0, 0, 0, true, false, 0, 1024);
    gemm(p_ps, gate_w, gate_b, p_gatepre, 1024,  512, 512, 512, 512,  512, 1.f, 1, 0, 0, 0, true, false);
    gemm(p_ps, hip_qw, hip_qb, p_qh,      1024,  512, 512, 512, 512,  512, 1.f, 1, 0, 0, 0, true, false);

    // linear attention == causal attention: S = q k^T (masked; masked tiles culled)
    gemm(p_qkv, p_qkv + 512, nullptr, p_S, 512, 512, 512, 1536, 1536, 512,
         1.f, 2, 512LL * 1536, 512LL * 1536, 512LL * 512, true, true);
    // num = S @ v -> combined[:, 1024:1536]  (K capped at m0+128)
    gemm(p_S, p_qkv + 1024, nullptr, p_comb + 1024, 512, 512, 512, 512, 1536, 2048,
         1.f, 2, 512LL * 512, 512LL * 1536, 512LL * 2048, false, false, 1, 0);
    den_div_kernel<<<BT, 256>>>();

    // intent = tanh(LN(gatepre)) -> combined[:, 512:1024]
    ln_kernel<<<BT, 256>>>(p_gatepre, gate_g, gate_bb, p_comb + 512, 2048, 0);

    // hippocampus: attn = softmax(qh @ mem^T / sqrt(D)); episodes = attn @ mem
    gemm(p_qh, mem_bank, nullptr, p_attn, 1024, 256, 512, 512, 512, 256,
         0.044194173824159216f, 1, 0, 0, 0, true, false);
    softmax_kernel<<<BT, 256>>>();
    gemm(p_attn, mem_bank, nullptr, p_comb + 1536, 1024, 512, 256, 256, 512, 2048,
         1.f, 1, 0, 0, 0, false, false);

    // thought = LN(tanh(combined @ axon_w^T + axon_b))
    gemm(p_comb, axon_w, axon_b, p_tpre, 1024, 512, 2048, 2048, 2048, 512,
         1.f, 1, 0, 0, 0, true, false);
    ln_kernel<<<BT, 256>>>(p_tpre, norm_g, norm_b, out_thought, 512, 1);

    // logits = (thought @ sw^T) * 16
    gemm(out_thought, p_sw, nullptr, out_logits, 1024, 256, 512, 512, 512, 256,
         16.f, 1, 0, 0, 0, true, false);
}

// round 14
// speedup vs baseline: 1.2500x; 1.2500x over previous
#include <cuda_runtime.h>
#include <math.h>

#define TT 512
#define DD 512
#define NBATCH 2
#define VV 256
#define MMEM 256
#define BT 1024
#define D3 1536
#define DOM_BLOCKS 64
#define UNITS 8
#define GRU_THREADS 384

// ---------------- static device scratch ----------------
__device__ float g_table[VV * D3];
__device__ float g_pf[BT * DD];
__device__ float g_ps[BT * DD];
__device__ float g_qkv[BT * D3];
__device__ float g_S[NBATCH * TT * TT];
__device__ float g_attn[BT * MMEM];
__device__ float g_comb[BT * 2048];
__device__ float g_tpre[BT * DD];
__device__ float g_gatepre[BT * DD];
__device__ float g_qh[BT * DD];
__device__ float g_sw[VV * DD];
__device__ float g_hf3[3][NBATCH * DD];
__device__ float g_hs3[3][NBATCH * DD];
__device__ unsigned g_barb[2][32];   // one counter per batch domain, 128B apart

// ---------------- block reductions ----------------
__device__ __forceinline__ float block_red_sum(float v, float* sb) {
    __syncthreads();
    int lane = threadIdx.x & 31, w = threadIdx.x >> 5;
    #pragma unroll
    for (int o = 16; o; o >>= 1) v += __shfl_xor_sync(0xffffffffu, v, o);
    if (lane == 0) sb[w] = v;
    __syncthreads();
    float r = (lane < (int)(blockDim.x >> 5)) ? sb[lane] : 0.f;
    #pragma unroll
    for (int o = 16; o; o >>= 1) r += __shfl_xor_sync(0xffffffffu, r, o);
    return r;
}

__device__ __forceinline__ float block_red_max(float v, float* sb) {
    __syncthreads();
    int lane = threadIdx.x & 31, w = threadIdx.x >> 5;
    #pragma unroll
    for (int o = 16; o; o >>= 1) v = fmaxf(v, __shfl_xor_sync(0xffffffffu, v, o));
    if (lane == 0) sb[w] = v;
    __syncthreads();
    float r = (lane < (int)(blockDim.x >> 5)) ? sb[lane] : -3.4e38f;
    #pragma unroll
    for (int o = 16; o; o >>= 1) r = fmaxf(r, __shfl_xor_sync(0xffffffffu, r, o));
    return r;
}

__global__ void reset_bar_kernel() { g_barb[0][0] = 0u; g_barb[1][0] = 0u; }

// ---------------- fast activations ----------------
__device__ __forceinline__ float sigf(float x) {
    return __fdividef(1.f, 1.f + __expf(-x));
}
__device__ __forceinline__ float tanhf_fast(float x) {
    float ax = fabsf(x);
    float t = __expf(-2.f * ax);
    float r = __fdividef(1.f - t, 1.f + t);
    return copysignf(r, x);
}

#define FMA2(d, a, b, c) \
    asm("fma.rn.f32x2 %0, %1, %2, %3;" : "=l"(d) : "l"(a), "l"(b), "l"(c))

// ---------------- batch-split fused GRU ----------------
// 128 blocks = 2 independent 64-block domains (one per batch), each with its own
// counter; NO cross-domain waits. Per block: 8 units, 12 warps = 3 trios x 4 slots,
// each warp does 2 units x 3 gates for its batch (weights in 96 regs/lane).
__global__ void __launch_bounds__(GRU_THREADS) fused_gru_kernel(
    const float* __restrict__ fast_whh, const float* __restrict__ fast_bhh,
    const float* __restrict__ slow_wih, const float* __restrict__ slow_bih,
    const float* __restrict__ slow_whh, const float* __restrict__ slow_bhh,
    const float* __restrict__ gi_table, const int* __restrict__ toks,
    const float* __restrict__ hf0, const float* __restrict__ hs0,
    float* __restrict__ pf, float* __restrict__ comb, float* __restrict__ ps,
    float* __restrict__ hfT, float* __restrict__ hsT)
{
    __shared__ float sg[3][3][UNITS];   // [trio][gate][unit]
    const int tid = threadIdx.x;
    const int w = tid >> 5, lane = tid & 31;
    const int dom = blockIdx.x >> 6;            // batch index
    const int blk = blockIdx.x & 63;
    const int ibase = blk * UNITS;
    const int tr = w >> 2, up = w & 3;          // trio, unit-pair slot
    unsigned* barp = &g_barb[dom][0];

    const float* Wsrc = (tr == 0) ? fast_whh : ((tr == 1) ? slow_wih : slow_whh);
    ulonglong2 wreg[2][3][4];
    #pragma unroll
    for (int uu = 0; uu < 2; uu++) {
        const int u = ibase + up * 2 + uu;
        #pragma unroll
        for (int g = 0; g < 3; g++)
            #pragma unroll
            for (int j = 0; j < 4; j++)
                wreg[uu][g][j] = *(const ulonglong2*)&Wsrc[(size_t)(g * DD + u) * DD + lane * 4 + j * 128];
    }

    const int ci = ibase + lane;                // cell unit (lane<8)
    float b_r = 0.f, b_z = 0.f, b_n = 0.f;      // fast bhh / slow bih
    float b2_r = 0.f, b2_z = 0.f, b2_n = 0.f;   // slow bhh
    if (w == 0 && lane < 8) {
        b_r = fast_bhh[ci]; b_z = fast_bhh[DD + ci]; b_n = fast_bhh[2 * DD + ci];
        g_hf3[0][dom * DD + ci] = hf0[dom * DD + ci];
    }
    if (w == 1 && lane < 8) {
        b_r = slow_bih[ci]; b_z = slow_bih[DD + ci]; b_n = slow_bih[2 * DD + ci];
        b2_r = slow_bhh[ci]; b2_z = slow_bhh[DD + ci]; b2_n = slow_bhh[2 * DD + ci];
        g_hs3[0][dom * DD + ci] = hs0[dom * DD + ci];
    }
    __syncthreads();
    if (tid == 0) {
        asm volatile("red.release.gpu.global.add.u32 [%0], 1;" :: "l"(barp) : "memory");
        unsigned v;
        do {
            asm volatile("ld.acquire.gpu.u32 %0, [%1];" : "=r"(v) : "l"(barp) : "memory");
        } while (v < DOM_BLOCKS);
    }
    __syncthreads();

    for (int t = 0; t <= TT; t++) {
        const int cur = t % 3, nxt = (t + 1) % 3;       // fast buffers
        const int cur_s = (t + 2) % 3, nxt_s = t % 3;   // slow buffers (step t-1)

        // cell prefetches
        float gr = 0.f, gz = 0.f, gn = 0.f, hprev = 0.f;
        if (w == 0 && lane < 8 && t < TT) {
            const int row = dom * TT + t;
            const float* gi = gi_table + (size_t)__ldg(&toks[row]) * D3;
            gr = __ldg(gi + ci); gz = __ldg(gi + DD + ci); gn = __ldg(gi + 2 * DD + ci);
            hprev = __ldcg(&g_hf3[cur][dom * DD + ci]);
        }
        if (w == 1 && lane < 8 && t >= 1)
            hprev = __ldcg(&g_hs3[cur_s][dom * DD + ci]);

        // this trio's input vector (one batch)
        const float* base;
        if (tr == 0)      base = &g_hf3[cur][dom * DD];
        else if (tr == 1) base = pf + (size_t)(dom * TT + ((t > 0) ? t - 1 : 0)) * DD;
        else              base = &g_hs3[cur_s][dom * DD];
        ulonglong2 xv[4];
        #pragma unroll
        for (int j = 0; j < 4; j++)
            xv[j] = __ldcg((const ulonglong2*)(base + lane * 4 + j * 128));

        // 6 dot products (2 units x 3 gates), packed f32x2
        unsigned long long acc2[2][3];
        #pragma unroll
        for (int uu = 0; uu < 2; uu++)
            #pragma unroll
            for (int g = 0; g < 3; g++) acc2[uu][g] = 0ull;
        #pragma unroll
        for (int j = 0; j < 4; j++)
            #pragma unroll
            for (int uu = 0; uu < 2; uu++)
                #pragma unroll
                for (int g = 0; g < 3; g++) {
                    FMA2(acc2[uu][g], wreg[uu][g][j].x, xv[j].x, acc2[uu][g]);
                    FMA2(acc2[uu][g], wreg[uu][g][j].y, xv[j].y, acc2[uu][g]);
                }

        float a[2][3];
        #pragma unroll
        for (int uu = 0; uu < 2; uu++)
            #pragma unroll
            for (int g = 0; g < 3; g++) {
                float lo, hi;
                asm("mov.b64 {%0, %1}, %2;" : "=f"(lo), "=f"(hi) : "l"(acc2[uu][g]));
                a[uu][g] = lo + hi;
            }
        #pragma unroll
        for (int o = 16; o; o >>= 1)
            #pragma unroll
            for (int uu = 0; uu < 2; uu++)
                #pragma unroll
                for (int g = 0; g < 3; g++)
                    a[uu][g] += __shfl_xor_sync(0xffffffffu, a[uu][g], o);

        if (lane == 0) {
            #pragma unroll
            for (int uu = 0; uu < 2; uu++)
                #pragma unroll
                for (int g = 0; g < 3; g++)
                    sg[tr][g][up * 2 + uu] = a[uu][g];
        }
        __syncthreads();

        if (w == 0 && lane < 8 && t < TT) {         // fast GRU step t
            const int row = dom * TT + t;
            float r = sigf(gr + sg[0][0][lane] + b_r);
            float z = sigf(gz + sg[0][1][lane] + b_z);
            float n = tanhf_fast(gn + r * (sg[0][2][lane] + b_n));
            float hnew = (1.f - z) * n + z * hprev;
            g_hf3[nxt][dom * DD + ci] = hnew;
            pf[(size_t)row * DD + ci] = hnew;
            comb[(size_t)row * 2048 + ci] = hnew;
            if (t == TT - 1) hfT[dom * DD + ci] = hnew;
        }
        if (w == 1 && lane < 8 && t >= 1) {         // slow GRU step t-1
            const int ts = t - 1, row = dom * TT + ts;
            float r = sigf(sg[1][0][lane] + b_r + sg[2][0][lane] + b2_r);
            float z = sigf(sg[1][1][lane] + b_z + sg[2][1][lane] + b2_z);
            float n = tanhf_fast(sg[1][2][lane] + b_n + r * (sg[2][2][lane] + b2_n));
            float hnew = (1.f - z) * n + z * hprev;
            g_hs3[nxt_s][dom * DD + ci] = hnew;
            ps[(size_t)row * DD + ci] = hnew;
            if (ts == TT - 1) hsT[dom * DD + ci] = hnew;
        }
        if (t < TT) {
            __syncthreads();
            if (tid == 0) {
                asm volatile("red.release.gpu.global.add.u32 [%0], 1;" :: "l"(barp) : "memory");
                unsigned target = (unsigned)(t + 2) * DOM_BLOCKS;
                unsigned v;
                do {
                    asm volatile("ld.acquire.gpu.u32 %0, [%1];" : "=r"(v) : "l"(barp) : "memory");
                } while (v < target);
            }
            __syncthreads();
        }
    }
}

// ---------------- GEMM: 128x64 tile, 256 thr, 8x4/thread, f32x2 FMA ----------------
// TB=true : Bm stored [N,K]  (C = A @ Bm^T);  TB=false: Bm stored [K,N]
// CAUSAL: zero where col > row; fully-masked tiles skip the K loop.
// klim != 0: cap K at m0+128.  elu_cols: elu(x)+1 on output cols < elu_cols.
template <bool TB, bool CAUSAL>
__global__ void __launch_bounds__(256) gemm_kernel(
    const float* __restrict__ A, const float* __restrict__ Bm,
    const float* __restrict__ bias, float* __restrict__ C,
    int M, int N, int K, int lda, int ldb, int ldc,
    long long sA, long long sB, long long sC, float scale,
    int klim, int elu_cols)
{
    __shared__ __align__(16) float As[2][16][132];
    __shared__ __align__(16) float Bs[2][16][68];
    const int z = blockIdx.z;
    A += (size_t)z * sA; Bm += (size_t)z * sB; C += (size_t)z * sC;
    const int m0 = blockIdx.y * 128, n0 = blockIdx.x * 64;
    const int tid = threadIdx.x;
    const int ty = tid >> 4, tx = tid & 15;
    const int nn = n0 + (tx << 2);

    if (CAUSAL && n0 > m0 + 127) {
        float4 zv = make_float4(0.f, 0.f, 0.f, 0.f);
        #pragma unroll
        for (int p2 = 0; p2 < 4; p2++)
            #pragma unroll
            for (int half = 0; half < 2; half++) {
                const int mm = m0 + (ty << 3) + (p2 << 1) + half;
                *(float4*)(C + (size_t)mm * ldc + nn) = zv;
            }
        return;
    }

    const int Kc = klim ? ((m0 + 128 < K) ? m0 + 128 : K) : K;
    const int ar = tid >> 2, ac = (tid & 3) << 2;
    const int bk = tid >> 4, bn = (tid & 15) << 2;

    float4 a0 = *(const float4*)(A + (size_t)(m0 + ar) * lda + ac);
    float4 a1 = *(const float4*)(A + (size_t)(m0 + ar + 64) * lda + ac);
    float4 bv;
    if (TB) bv = *(const float4*)(Bm + (size_t)(n0 + ar) * ldb + ac);
    else    bv = *(const float4*)(Bm + (size_t)bk * ldb + n0 + bn);

    {
        As[0][ac + 0][ar] = a0.x; As[0][ac + 1][ar] = a0.y;
        As[0][ac + 2][ar] = a0.z; As[0][ac + 3][ar] = a0.w;
        As[0][ac + 0][ar + 64] = a1.x; As[0][ac + 1][ar + 64] = a1.y;
        As[0][ac + 2][ar + 64] = a1.z; As[0][ac + 3][ar + 64] = a1.w;
        if (TB) {
            Bs[0][ac + 0][ar] = bv.x; Bs[0][ac + 1][ar] = bv.y;
            Bs[0][ac + 2][ar] = bv.z; Bs[0][ac + 3][ar] = bv.w;
        } else {
            *(float4*)&Bs[0][bk][bn] = bv;
        }
    }
    __syncthreads();

    unsigned long long acc[4][4];
    #pragma unroll
    for (int p2 = 0; p2 < 4; p2++)
        #pragma unroll
        for (int jj = 0; jj < 4; jj++) acc[p2][jj] = 0ull;

    const int P = Kc >> 4;
    int buf = 0;
    for (int p = 0; p < P; p++) {
        if (p + 1 < P) {
            const int k0n = (p + 1) << 4;
            a0 = *(const float4*)(A + (size_t)(m0 + ar) * lda + k0n + ac);
            a1 = *(const float4*)(A + (size_t)(m0 + ar + 64) * lda + k0n + ac);
            if (TB) bv = *(const float4*)(Bm + (size_t)(n0 + ar) * ldb + k0n + ac);
            else    bv = *(const float4*)(Bm + (size_t)(k0n + bk) * ldb + n0 + bn);
        }
        #pragma unroll
        for (int k = 0; k < 16; k++) {
            ulonglong2 alo = *(const ulonglong2*)&As[buf][k][ty << 3];
            ulonglong2 ahi = *(const ulonglong2*)&As[buf][k][(ty << 3) + 4];
            float4 b4 = *(const float4*)&Bs[buf][k][tx << 2];
            unsigned long long bd[4];
            asm("mov.b64 %0, {%1, %1};" : "=l"(bd[0]) : "f"(b4.x));
            asm("mov.b64 %0, {%1, %1};" : "=l"(bd[1]) : "f"(b4.y));
            asm("mov.b64 %0, {%1, %1};" : "=l"(bd[2]) : "f"(b4.z));
            asm("mov.b64 %0, {%1, %1};" : "=l"(bd[3]) : "f"(b4.w));
            #pragma unroll
            for (int jj = 0; jj < 4; jj++) {
                FMA2(acc[0][jj], alo.x, bd[jj], acc[0][jj]);
                FMA2(acc[1][jj], alo.y, bd[jj], acc[1][jj]);
                FMA2(acc[2][jj], ahi.x, bd[jj], acc[2][jj]);
                FMA2(acc[3][jj], ahi.y, bd[jj], acc[3][jj]);
            }
        }
        if (p + 1 < P) {
            const int nb = buf ^ 1;
            As[nb][ac + 0][ar] = a0.x; As[nb][ac + 1][ar] = a0.y;
            As[nb][ac + 2][ar] = a0.z; As[nb][ac + 3][ar] = a0.w;
            As[nb][ac + 0][ar + 64] = a1.x; As[nb][ac + 1][ar + 64] = a1.y;
            As[nb][ac + 2][ar + 64] = a1.z; As[nb][ac + 3][ar + 64] = a1.w;
            if (TB) {
                Bs[nb][ac + 0][ar] = bv.x; Bs[nb][ac + 1][ar] = bv.y;
                Bs[nb][ac + 2][ar] = bv.z; Bs[nb][ac + 3][ar] = bv.w;
            } else {
                *(float4*)&Bs[nb][bk][bn] = bv;
            }
            __syncthreads();
            buf = nb;
        }
    }

    float4 bvec;
    if (bias) bvec = *(const float4*)&bias[nn];
    #pragma unroll
    for (int p2 = 0; p2 < 4; p2++) {
        float rlo[4], rhi[4];
        #pragma unroll
        for (int jj = 0; jj < 4; jj++) {
            float lo, hi;
            asm("mov.b64 {%0, %1}, %2;" : "=f"(lo), "=f"(hi) : "l"(acc[p2][jj]));
            rlo[jj] = lo; rhi[jj] = hi;
        }
        #pragma unroll
        for (int half = 0; half < 2; half++) {
            const int mm = m0 + (ty << 3) + (p2 << 1) + half;
            float* rr = half ? rhi : rlo;
            float4 cv;
            cv.x = rr[0] * scale; cv.y = rr[1] * scale;
            cv.z = rr[2] * scale; cv.w = rr[3] * scale;
            if (bias) { cv.x += bvec.x; cv.y += bvec.y; cv.z += bvec.z; cv.w += bvec.w; }
            if (elu_cols) {
                if (nn + 0 < elu_cols) cv.x = cv.x > 0.f ? cv.x + 1.f : __expf(cv.x);
                if (nn + 1 < elu_cols) cv.y = cv.y > 0.f ? cv.y + 1.f : __expf(cv.y);
                if (nn + 2 < elu_cols) cv.z = cv.z > 0.f ? cv.z + 1.f : __expf(cv.z);
                if (nn + 3 < elu_cols) cv.w = cv.w > 0.f ? cv.w + 1.f : __expf(cv.w);
            }
            if (CAUSAL) {
                if (nn + 0 > mm) cv.x = 0.f;
                if (nn + 1 > mm) cv.y = 0.f;
                if (nn + 2 > mm) cv.z = 0.f;
                if (nn + 3 > mm) cv.w = 0.f;
            }
            *(float4*)(C + (size_t)mm * ldc + nn) = cv;
        }
    }
}

// ---------------- small kernels ----------------
__global__ void den_div_kernel() {
    __shared__ float sb[32];
    int row = blockIdx.x;
    float s = 0.f;
    for (int c = threadIdx.x; c < TT; c += 256) s += g_S[(size_t)row * TT + c];
    s = block_red_sum(s, sb);
    float inv = __fdividef(1.f, s + 1e-6f);
    for (int j = threadIdx.x; j < DD; j += 256)
        g_comb[(size_t)row * 2048 + 1024 + j] *= inv;
}

__global__ void softmax_kernel() {
    __shared__ float sb[32];
    int row = blockIdx.x;
    float x = g_attn[(size_t)row * MMEM + threadIdx.x];
    float m = block_red_max(x, sb);
    float e = __expf(x - m);
    float s = block_red_sum(e, sb);
    g_attn[(size_t)row * MMEM + threadIdx.x] = e / s;
}

__device__ __forceinline__ float tanh_bulk(float x) {
    float ax = fabsf(x);
    float t = __expf(-2.f * ax);
    float r = __fdividef(1.f - t, 1.f + t);
    return copysignf(r, x);
}

// mode 0: out = tanh(LN(in));  mode 1: out = LN(tanh(in))
__global__ void ln_kernel(const float* __restrict__ in, const float* __restrict__ gg,
                          const float* __restrict__ bb, float* __restrict__ out,
                          int ldo, int mode)
{
    __shared__ float sb[32];
    int row = blockIdx.x, tid = threadIdx.x;
    float x0 = in[(size_t)row * DD + tid];
    float x1 = in[(size_t)row * DD + 256 + tid];
    if (mode == 1) { x0 = tanh_bulk(x0); x1 = tanh_bulk(x1); }
    float s  = block_red_sum(x0 + x1, sb);
    float sq = block_red_sum(x0 * x0 + x1 * x1, sb);
    float mean = s * (1.f / 512.f);
    float var  = sq * (1.f / 512.f) - mean * mean;
    float rstd = rsqrtf(var + 1e-5f);
    float y0 = (x0 - mean) * rstd * gg[tid] + bb[tid];
    float y1 = (x1 - mean) * rstd * gg[256 + tid] + bb[256 + tid];
    if (mode == 0) { y0 = tanh_bulk(y0); y1 = tanh_bulk(y1); }
    out[(size_t)row * ldo + tid] = y0;
    out[(size_t)row * ldo + 256 + tid] = y1;
}

__global__ void rownorm_kernel(const float* __restrict__ src) {
    __shared__ float sb[32];
    int row = blockIdx.x, tid = threadIdx.x;
    float x0 = src[(size_t)row * DD + tid];
    float x1 = src[(size_t)row * DD + 256 + tid];
    float ss = block_red_sum(x0 * x0 + x1 * x1, sb);
    float inv = 1.f / fmaxf(sqrtf(ss), 1e-12f);
    g_sw[(size_t)row * DD + tid] = x0 * inv;
    g_sw[(size_t)row * DD + 256 + tid] = x1 * inv;
}

// ---------------- host ----------------
static inline void gemm(const float* A, const float* B, const float* bias, float* C,
                        int M, int N, int K, int lda, int ldb, int ldc,
                        float scale, int batch, long long sA, long long sB, long long sC,
                        bool tb, bool causal, int klim = 0, int elu_cols = 0)
{
    dim3 grid(N / 64, M / 128, batch);
    if (tb) {
        if (causal)
            gemm_kernel<true, true><<<grid, 256>>>(A, B, bias, C, M, N, K, lda, ldb, ldc, sA, sB, sC, scale, klim, elu_cols);
        else
            gemm_kernel<true, false><<<grid, 256>>>(A, B, bias, C, M, N, K, lda, ldb, ldc, sA, sB, sC, scale, klim, elu_cols);
    } else {
        gemm_kernel<false, false><<<grid, 256>>>(A, B, bias, C, M, N, K, lda, ldb, ldc, sA, sB, sC, scale, klim, elu_cols);
    }
}

extern "C" void kernel_launch(void* const* d_in, const int* in_sizes, int n_in,
                              void* d_out, int out_size)
{
    (void)in_sizes; (void)n_in; (void)out_size;
    const int*   x        = (const int*)d_in[0];
    const float* h_f      = (const float*)d_in[1];
    const float* h_s      = (const float*)d_in[2];
    const float* soma_w   = (const float*)d_in[3];
    const float* fast_wih = (const float*)d_in[4];
    const float* fast_whh = (const float*)d_in[5];
    const float* fast_bih = (const float*)d_in[6];
    const float* fast_bhh = (const float*)d_in[7];
    const float* slow_wih = (const float*)d_in[8];
    const float* slow_whh = (const float*)d_in[9];
    const float* slow_bih = (const float*)d_in[10];
    const float* slow_bhh = (const float*)d_in[11];
    const float* qkv_w    = (const float*)d_in[12];
    const float* qkv_b    = (const float*)d_in[13];
    const float* gate_w   = (const float*)d_in[14];
    const float* gate_b   = (const float*)d_in[15];
    const float* gate_g   = (const float*)d_in[16];
    const float* gate_bb  = (const float*)d_in[17];
    const float* mem_bank = (const float*)d_in[18];
    const float* hip_qw   = (const float*)d_in[19];
    const float* hip_qb   = (const float*)d_in[20];
    const float* axon_w   = (const float*)d_in[21];
    const float* axon_b   = (const float*)d_in[22];
    const float* norm_g   = (const float*)d_in[23];
    const float* norm_b   = (const float*)d_in[24];

    float* out = (float*)d_out;
    float* out_logits  = out;            // [B,T,V]
    float* out_thought = out + 262144;   // [B,T,D]
    float* out_hf      = out + 786432;   // [1,B,D]
    float* out_hs      = out + 787456;   // [1,B,D]

    float *p_table, *p_pf, *p_ps, *p_qkv, *p_S, *p_attn, *p_comb,
          *p_tpre, *p_gatepre, *p_qh, *p_sw;
    cudaGetSymbolAddress((void**)&p_table,   g_table);
    cudaGetSymbolAddress((void**)&p_pf,      g_pf);
    cudaGetSymbolAddress((void**)&p_ps,      g_ps);
    cudaGetSymbolAddress((void**)&p_qkv,     g_qkv);
    cudaGetSymbolAddress((void**)&p_S,       g_S);
    cudaGetSymbolAddress((void**)&p_attn,    g_attn);
    cudaGetSymbolAddress((void**)&p_comb,    g_comb);
    cudaGetSymbolAddress((void**)&p_tpre,    g_tpre);
    cudaGetSymbolAddress((void**)&p_gatepre, g_gatepre);
    cudaGetSymbolAddress((void**)&p_qh,      g_qh);
    cudaGetSymbolAddress((void**)&p_sw,      g_sw);

    // normalized embedding rows for logits
    rownorm_kernel<<<VV, 256>>>(soma_w);

    // fast-GRU input-gate token table: [V,3D] = soma_w @ fast_wih^T + fast_bih
    gemm(soma_w, fast_wih, fast_bih, p_table, 256, 1536, 512, 512, 512, 1536,
         1.f, 1, 0, 0, 0, true, false);

    // reset counters BEFORE the GRU (keeps fused_gru in the ncu window)
    reset_bar_kernel<<<1, 1>>>();

    // batch-split fused GRUs -> p_f, comb[:,0:512], p_s, hf1, hs1
    fused_gru_kernel<<<2 * DOM_BLOCKS, GRU_THREADS>>>(
        fast_whh, fast_bhh, slow_wih, slow_bih, slow_whh, slow_bhh,
        p_table, x, h_f, h_s, p_pf, p_comb, p_ps, out_hf, out_hs);

    // projections from p_s (elu fused into qkv epilogue for q,k cols)
    gemm(p_ps, qkv_w,  qkv_b,  p_qkv,     1024, 1536, 512, 512, 512, 1536, 1.f, 1, 0, 0, 0, true, false, 0, 1024);
    gemm(p_ps, gate_w, gate_b, p_gatepre, 1024,  512, 512, 512, 512,  512, 1.f, 1, 0, 0, 0, true, false);
    gemm(p_ps, hip_qw, hip_qb, p_qh,      1024,  512, 512, 512, 512,  512, 1.f, 1, 0, 0, 0, true, false);

    // linear attention == causal attention: S = q k^T (masked; masked tiles culled)
    gemm(p_qkv, p_qkv + 512, nullptr, p_S, 512, 512, 512, 1536, 1536, 512,
         1.f, 2, 512LL * 1536, 512LL * 1536, 512LL * 512, true, true);
    // num = S @ v -> combined[:, 1024:1536]  (K capped at m0+128)
    gemm(p_S, p_qkv + 1024, nullptr, p_comb + 1024, 512, 512, 512, 512, 1536, 2048,
         1.f, 2, 512LL * 512, 512LL * 1536, 512LL * 2048, false, false, 1, 0);
    den_div_kernel<<<BT, 256>>>();

    // intent = tanh(LN(gatepre)) -> combined[:, 512:1024]
    ln_kernel<<<BT, 256>>>(p_gatepre, gate_g, gate_bb, p_comb + 512, 2048, 0);

    // hippocampus: attn = softmax(qh @ mem^T / sqrt(D)); episodes = attn @ mem
    gemm(p_qh, mem_bank, nullptr, p_attn, 1024, 256, 512, 512, 512, 256,
         0.044194173824159216f, 1, 0, 0, 0, true, false);
    softmax_kernel<<<BT, 256>>>();
    gemm(p_attn, mem_bank, nullptr, p_comb + 1536, 1024, 512, 256, 256, 512, 2048,
         1.f, 1, 0, 0, 0, false, false);

    // thought = LN(tanh(combined @ axon_w^T + axon_b))
    gemm(p_comb, axon_w, axon_b, p_tpre, 1024, 512, 2048, 2048, 2048, 512,
         1.f, 1, 0, 0, 0, true, false);
    ln_kernel<<<BT, 256>>>(p_tpre, norm_g, norm_b, out_thought, 512, 1);

    // logits = (thought @ sw^T) * 16
    gemm(out_thought, p_sw, nullptr, out_logits, 1024, 256, 512, 512, 512, 256,
         16.f, 1, 0, 0, 0, true, false);
}

// round 15
// speedup vs baseline: 1.3694x; 1.0955x over previous
#include <cuda_runtime.h>
#include <math.h>

#define TT 512
#define DD 512
#define NBATCH 2
#define VV 256
#define MMEM 256
#define BT 1024
#define D3 1536
#define DOM_BLOCKS 64
#define UNITS 8
#define GRU_THREADS 384

// ---------------- static device scratch ----------------
__device__ float g_table[VV * D3];
__device__ float g_pf[BT * DD];
__device__ float g_ps[BT * DD];
__device__ float g_qkv[BT * D3];
__device__ float g_S[NBATCH * TT * TT];
__device__ float g_attn[BT * MMEM];
__device__ float g_comb[BT * 2048];
__device__ float g_tpre[BT * DD];
__device__ float g_gatepre[BT * DD];
__device__ float g_qh[BT * DD];
__device__ float g_sw[VV * DD];
__device__ float g_hf3[3][NBATCH * DD];
__device__ float g_hs3[3][NBATCH * DD];
__device__ unsigned g_barb[2][32];   // one counter per batch domain, 128B apart

// ---------------- block reductions ----------------
__device__ __forceinline__ float block_red_sum(float v, float* sb) {
    __syncthreads();
    int lane = threadIdx.x & 31, w = threadIdx.x >> 5;
    #pragma unroll
    for (int o = 16; o; o >>= 1) v += __shfl_xor_sync(0xffffffffu, v, o);
    if (lane == 0) sb[w] = v;
    __syncthreads();
    float r = (lane < (int)(blockDim.x >> 5)) ? sb[lane] : 0.f;
    #pragma unroll
    for (int o = 16; o; o >>= 1) r += __shfl_xor_sync(0xffffffffu, r, o);
    return r;
}

__device__ __forceinline__ float block_red_max(float v, float* sb) {
    __syncthreads();
    int lane = threadIdx.x & 31, w = threadIdx.x >> 5;
    #pragma unroll
    for (int o = 16; o; o >>= 1) v = fmaxf(v, __shfl_xor_sync(0xffffffffu, v, o));
    if (lane == 0) sb[w] = v;
    __syncthreads();
    float r = (lane < (int)(blockDim.x >> 5)) ? sb[lane] : -3.4e38f;
    #pragma unroll
    for (int o = 16; o; o >>= 1) r = fmaxf(r, __shfl_xor_sync(0xffffffffu, r, o));
    return r;
}

__global__ void reset_bar_kernel() { g_barb[0][0] = 0u; g_barb[1][0] = 0u; }

// ---------------- fast activations ----------------
__device__ __forceinline__ float sigf(float x) {
    return __fdividef(1.f, 1.f + __expf(-x));
}
__device__ __forceinline__ float tanhf_fast(float x) {
    float ax = fabsf(x);
    float t = __expf(-2.f * ax);
    float r = __fdividef(1.f - t, 1.f + t);
    return copysignf(r, x);
}

#define FMA2(d, a, b, c) \
    asm("fma.rn.f32x2 %0, %1, %2, %3;" : "=l"(d) : "l"(a), "l"(b), "l"(c))

// ---------------- batch-split fused GRU (R14 + register-carried cell state) ----------------
__global__ void __launch_bounds__(GRU_THREADS) fused_gru_kernel(
    const float* __restrict__ fast_whh, const float* __restrict__ fast_bhh,
    const float* __restrict__ slow_wih, const float* __restrict__ slow_bih,
    const float* __restrict__ slow_whh, const float* __restrict__ slow_bhh,
    const float* __restrict__ gi_table, const int* __restrict__ toks,
    const float* __restrict__ hf0, const float* __restrict__ hs0,
    float* __restrict__ pf, float* __restrict__ comb, float* __restrict__ ps,
    float* __restrict__ hfT, float* __restrict__ hsT)
{
    __shared__ float sg[3][3][UNITS];   // [trio][gate][unit]
    const int tid = threadIdx.x;
    const int w = tid >> 5, lane = tid & 31;
    const int dom = blockIdx.x >> 6;
    const int blk = blockIdx.x & 63;
    const int ibase = blk * UNITS;
    const int tr = w >> 2, up = w & 3;
    unsigned* barp = &g_barb[dom][0];

    const float* Wsrc = (tr == 0) ? fast_whh : ((tr == 1) ? slow_wih : slow_whh);
    ulonglong2 wreg[2][3][4];
    #pragma unroll
    for (int uu = 0; uu < 2; uu++) {
        const int u = ibase + up * 2 + uu;
        #pragma unroll
        for (int g = 0; g < 3; g++)
            #pragma unroll
            for (int j = 0; j < 4; j++)
                wreg[uu][g][j] = *(const ulonglong2*)&Wsrc[(size_t)(g * DD + u) * DD + lane * 4 + j * 128];
    }

    const int ci = ibase + lane;                // cell unit (lane<8)
    float b_r = 0.f, b_z = 0.f, b_n = 0.f;
    float b2_r = 0.f, b2_z = 0.f, b2_n = 0.f;
    float hprev = 0.f;                           // register-carried cell state
    if (w == 0 && lane < 8) {
        b_r = fast_bhh[ci]; b_z = fast_bhh[DD + ci]; b_n = fast_bhh[2 * DD + ci];
        hprev = hf0[dom * DD + ci];
        g_hf3[0][dom * DD + ci] = hprev;
    }
    if (w == 1 && lane < 8) {
        b_r = slow_bih[ci]; b_z = slow_bih[DD + ci]; b_n = slow_bih[2 * DD + ci];
        b2_r = slow_bhh[ci]; b2_z = slow_bhh[DD + ci]; b2_n = slow_bhh[2 * DD + ci];
        hprev = hs0[dom * DD + ci];
        g_hs3[0][dom * DD + ci] = hprev;
    }
    __syncthreads();
    if (tid == 0) {
        asm volatile("red.release.gpu.global.add.u32 [%0], 1;" :: "l"(barp) : "memory");
        unsigned v;
        do {
            asm volatile("ld.acquire.gpu.u32 %0, [%1];" : "=r"(v) : "l"(barp) : "memory");
        } while (v < DOM_BLOCKS);
    }
    __syncthreads();

    for (int t = 0; t <= TT; t++) {
        const int cur = t % 3, nxt = (t + 1) % 3;
        const int cur_s = (t + 2) % 3, nxt_s = t % 3;

        float gr = 0.f, gz = 0.f, gn = 0.f;
        if (w == 0 && lane < 8 && t < TT) {
            const int row = dom * TT + t;
            const float* gi = gi_table + (size_t)__ldg(&toks[row]) * D3;
            gr = __ldg(gi + ci); gz = __ldg(gi + DD + ci); gn = __ldg(gi + 2 * DD + ci);
        }

        const float* base;
        if (tr == 0)      base = &g_hf3[cur][dom * DD];
        else if (tr == 1) base = pf + (size_t)(dom * TT + ((t > 0) ? t - 1 : 0)) * DD;
        else              base = &g_hs3[cur_s][dom * DD];
        ulonglong2 xv[4];
        #pragma unroll
        for (int j = 0; j < 4; j++)
            xv[j] = __ldcg((const ulonglong2*)(base + lane * 4 + j * 128));

        unsigned long long acc2[2][3];
        #pragma unroll
        for (int uu = 0; uu < 2; uu++)
            #pragma unroll
            for (int g = 0; g < 3; g++) acc2[uu][g] = 0ull;
        #pragma unroll
        for (int j = 0; j < 4; j++)
            #pragma unroll
            for (int uu = 0; uu < 2; uu++)
                #pragma unroll
                for (int g = 0; g < 3; g++) {
                    FMA2(acc2[uu][g], wreg[uu][g][j].x, xv[j].x, acc2[uu][g]);
                    FMA2(acc2[uu][g], wreg[uu][g][j].y, xv[j].y, acc2[uu][g]);
                }

        float a[2][3];
        #pragma unroll
        for (int uu = 0; uu < 2; uu++)
            #pragma unroll
            for (int g = 0; g < 3; g++) {
                float lo, hi;
                asm("mov.b64 {%0, %1}, %2;" : "=f"(lo), "=f"(hi) : "l"(acc2[uu][g]));
                a[uu][g] = lo + hi;
            }
        #pragma unroll
        for (int o = 16; o; o >>= 1)
            #pragma unroll
            for (int uu = 0; uu < 2; uu++)
                #pragma unroll
                for (int g = 0; g < 3; g++)
                    a[uu][g] += __shfl_xor_sync(0xffffffffu, a[uu][g], o);

        if (lane == 0) {
            #pragma unroll
            for (int uu = 0; uu < 2; uu++)
                #pragma unroll
                for (int g = 0; g < 3; g++)
                    sg[tr][g][up * 2 + uu] = a[uu][g];
        }
        __syncthreads();

        if (w == 0 && lane < 8 && t < TT) {         // fast GRU step t
            const int row = dom * TT + t;
            float r = sigf(gr + sg[0][0][lane] + b_r);
            float z = sigf(gz + sg[0][1][lane] + b_z);
            float n = tanhf_fast(gn + r * (sg[0][2][lane] + b_n));
            float hnew = (1.f - z) * n + z * hprev;
            hprev = hnew;
            g_hf3[nxt][dom * DD + ci] = hnew;
            pf[(size_t)row * DD + ci] = hnew;
            comb[(size_t)row * 2048 + ci] = hnew;
            if (t == TT - 1) hfT[dom * DD + ci] = hnew;
        }
        if (w == 1 && lane < 8 && t >= 1) {         // slow GRU step t-1
            const int ts = t - 1, row = dom * TT + ts;
            float r = sigf(sg[1][0][lane] + b_r + sg[2][0][lane] + b2_r);
            float z = sigf(sg[1][1][lane] + b_z + sg[2][1][lane] + b2_z);
            float n = tanhf_fast(sg[1][2][lane] + b_n + r * (sg[2][2][lane] + b2_n));
            float hnew = (1.f - z) * n + z * hprev;
            hprev = hnew;
            g_hs3[nxt_s][dom * DD + ci] = hnew;
            ps[(size_t)row * DD + ci] = hnew;
            if (ts == TT - 1) hsT[dom * DD + ci] = hnew;
        }
        if (t < TT) {
            __syncthreads();
            if (tid == 0) {
                asm volatile("red.release.gpu.global.add.u32 [%0], 1;" :: "l"(barp) : "memory");
                unsigned target = (unsigned)(t + 2) * DOM_BLOCKS;
                unsigned v;
                do {
                    asm volatile("ld.acquire.gpu.u32 %0, [%1];" : "=r"(v) : "l"(barp) : "memory");
                } while (v < target);
            }
            __syncthreads();
        }
    }
}

// ---------------- GEMM: MT x 64 tile (MT=128 or 64), 256 thr, f32x2 FMA ----------------
// TB=true : Bm stored [N,K]  (C = A @ Bm^T);  TB=false: Bm stored [K,N]
// CAUSAL: zero where col > row; fully-masked tiles skip the K loop.
// klim != 0: cap K at m0+MT.  elu_cols: elu(x)+1 on output cols < elu_cols.
template <int MT, bool TB, bool CAUSAL>
__global__ void __launch_bounds__(256) gemm_kernel(
    const float* __restrict__ A, const float* __restrict__ Bm,
    const float* __restrict__ bias, float* __restrict__ C,
    int M, int N, int K, int lda, int ldb, int ldc,
    long long sA, long long sB, long long sC, float scale,
    int klim, int elu_cols)
{
    constexpr int RP = MT / 32;                 // row-pairs per thread (128->4, 64->2)
    __shared__ __align__(16) float As[2][16][MT + 4];
    __shared__ __align__(16) float Bs[2][16][68];
    const int z = blockIdx.z;
    A += (size_t)z * sA; Bm += (size_t)z * sB; C += (size_t)z * sC;
    const int m0 = blockIdx.y * MT, n0 = blockIdx.x * 64;
    const int tid = threadIdx.x;
    const int ty = tid >> 4, tx = tid & 15;
    const int nn = n0 + (tx << 2);

    if (CAUSAL && n0 > m0 + MT - 1) {
        float4 zv = make_float4(0.f, 0.f, 0.f, 0.f);
        #pragma unroll
        for (int p2 = 0; p2 < RP; p2++)
            #pragma unroll
            for (int half = 0; half < 2; half++) {
                const int mm = m0 + ty * 2 * RP + (p2 << 1) + half;
                *(float4*)(C + (size_t)mm * ldc + nn) = zv;
            }
        return;
    }

    const int Kc = klim ? ((m0 + MT < K) ? m0 + MT : K) : K;
    const int ar = tid >> 2, ac = (tid & 3) << 2;
    const int bk = tid >> 4, bn = (tid & 15) << 2;

    float4 a0 = *(const float4*)(A + (size_t)(m0 + ar) * lda + ac);
    float4 a1;
    if (MT == 128) a1 = *(const float4*)(A + (size_t)(m0 + ar + 64) * lda + ac);
    float4 bv;
    if (TB) bv = *(const float4*)(Bm + (size_t)(n0 + ar) * ldb + ac);
    else    bv = *(const float4*)(Bm + (size_t)bk * ldb + n0 + bn);

    {
        As[0][ac + 0][ar] = a0.x; As[0][ac + 1][ar] = a0.y;
        As[0][ac + 2][ar] = a0.z; As[0][ac + 3][ar] = a0.w;
        if (MT == 128) {
            As[0][ac + 0][ar + 64] = a1.x; As[0][ac + 1][ar + 64] = a1.y;
            As[0][ac + 2][ar + 64] = a1.z; As[0][ac + 3][ar + 64] = a1.w;
        }
        if (TB) {
            Bs[0][ac + 0][ar] = bv.x; Bs[0][ac + 1][ar] = bv.y;
            Bs[0][ac + 2][ar] = bv.z; Bs[0][ac + 3][ar] = bv.w;
        } else {
            *(float4*)&Bs[0][bk][bn] = bv;
        }
    }
    __syncthreads();

    unsigned long long acc[RP][4];
    #pragma unroll
    for (int p2 = 0; p2 < RP; p2++)
        #pragma unroll
        for (int jj = 0; jj < 4; jj++) acc[p2][jj] = 0ull;

    const int P = Kc >> 4;
    int buf = 0;
    for (int p = 0; p < P; p++) {
        if (p + 1 < P) {
            const int k0n = (p + 1) << 4;
            a0 = *(const float4*)(A + (size_t)(m0 + ar) * lda + k0n + ac);
            if (MT == 128) a1 = *(const float4*)(A + (size_t)(m0 + ar + 64) * lda + k0n + ac);
            if (TB) bv = *(const float4*)(Bm + (size_t)(n0 + ar) * ldb + k0n + ac);
            else    bv = *(const float4*)(Bm + (size_t)(k0n + bk) * ldb + n0 + bn);
        }
        #pragma unroll
        for (int k = 0; k < 16; k++) {
            ulonglong2 af[RP / 2];
            af[0] = *(const ulonglong2*)&As[buf][k][ty * 2 * RP];
            if (RP == 4) af[1] = *(const ulonglong2*)&As[buf][k][ty * 2 * RP + 4];
            float4 b4 = *(const float4*)&Bs[buf][k][tx << 2];
            unsigned long long bd[4];
            asm("mov.b64 %0, {%1, %1};" : "=l"(bd[0]) : "f"(b4.x));
            asm("mov.b64 %0, {%1, %1};" : "=l"(bd[1]) : "f"(b4.y));
            asm("mov.b64 %0, {%1, %1};" : "=l"(bd[2]) : "f"(b4.z));
            asm("mov.b64 %0, {%1, %1};" : "=l"(bd[3]) : "f"(b4.w));
            #pragma unroll
            for (int p2 = 0; p2 < RP; p2++) {
                unsigned long long av = (p2 & 1) ? af[p2 >> 1].y : af[p2 >> 1].x;
                #pragma unroll
                for (int jj = 0; jj < 4; jj++)
                    FMA2(acc[p2][jj], av, bd[jj], acc[p2][jj]);
            }
        }
        if (p + 1 < P) {
            const int nb = buf ^ 1;
            As[nb][ac + 0][ar] = a0.x; As[nb][ac + 1][ar] = a0.y;
            As[nb][ac + 2][ar] = a0.z; As[nb][ac + 3][ar] = a0.w;
            if (MT == 128) {
                As[nb][ac + 0][ar + 64] = a1.x; As[nb][ac + 1][ar + 64] = a1.y;
                As[nb][ac + 2][ar + 64] = a1.z; As[nb][ac + 3][ar + 64] = a1.w;
            }
            if (TB) {
                Bs[nb][ac + 0][ar] = bv.x; Bs[nb][ac + 1][ar] = bv.y;
                Bs[nb][ac + 2][ar] = bv.z; Bs[nb][ac + 3][ar] = bv.w;
            } else {
                *(float4*)&Bs[nb][bk][bn] = bv;
            }
            __syncthreads();
            buf = nb;
        }
    }

    float4 bvec;
    if (bias) bvec = *(const float4*)&bias[nn];
    #pragma unroll
    for (int p2 = 0; p2 < RP; p2++) {
        float rlo[4], rhi[4];
        #pragma unroll
        for (int jj = 0; jj < 4; jj++) {
            float lo, hi;
            asm("mov.b64 {%0, %1}, %2;" : "=f"(lo), "=f"(hi) : "l"(acc[p2][jj]));
            rlo[jj] = lo; rhi[jj] = hi;
        }
        #pragma unroll
        for (int half = 0; half < 2; half++) {
            const int mm = m0 + ty * 2 * RP + (p2 << 1) + half;
            float* rr = half ? rhi : rlo;
            float4 cv;
            cv.x = rr[0] * scale; cv.y = rr[1] * scale;
            cv.z = rr[2] * scale; cv.w = rr[3] * scale;
            if (bias) { cv.x += bvec.x; cv.y += bvec.y; cv.z += bvec.z; cv.w += bvec.w; }
            if (elu_cols) {
                if (nn + 0 < elu_cols) cv.x = cv.x > 0.f ? cv.x + 1.f : __expf(cv.x);
                if (nn + 1 < elu_cols) cv.y = cv.y > 0.f ? cv.y + 1.f : __expf(cv.y);
                if (nn + 2 < elu_cols) cv.z = cv.z > 0.f ? cv.z + 1.f : __expf(cv.z);
                if (nn + 3 < elu_cols) cv.w = cv.w > 0.f ? cv.w + 1.f : __expf(cv.w);
            }
            if (CAUSAL) {
                if (nn + 0 > mm) cv.x = 0.f;
                if (nn + 1 > mm) cv.y = 0.f;
                if (nn + 2 > mm) cv.z = 0.f;
                if (nn + 3 > mm) cv.w = 0.f;
            }
            *(float4*)(C + (size_t)mm * ldc + nn) = cv;
        }
    }
}

// ---------------- small kernels ----------------
__global__ void den_div_kernel() {
    __shared__ float sb[32];
    int row = blockIdx.x;
    float s = 0.f;
    for (int c = threadIdx.x; c < TT; c += 256) s += g_S[(size_t)row * TT + c];
    s = block_red_sum(s, sb);
    float inv = __fdividef(1.f, s + 1e-6f);
    for (int j = threadIdx.x; j < DD; j += 256)
        g_comb[(size_t)row * 2048 + 1024 + j] *= inv;
}

__global__ void softmax_kernel() {
    __shared__ float sb[32];
    int row = blockIdx.x;
    float x = g_attn[(size_t)row * MMEM + threadIdx.x];
    float m = block_red_max(x, sb);
    float e = __expf(x - m);
    float s = block_red_sum(e, sb);
    g_attn[(size_t)row * MMEM + threadIdx.x] = e / s;
}

__device__ __forceinline__ float tanh_bulk(float x) {
    float ax = fabsf(x);
    float t = __expf(-2.f * ax);
    float r = __fdividef(1.f - t, 1.f + t);
    return copysignf(r, x);
}

// mode 0: out = tanh(LN(in));  mode 1: out = LN(tanh(in))
__global__ void ln_kernel(const float* __restrict__ in, const float* __restrict__ gg,
                          const float* __restrict__ bb, float* __restrict__ out,
                          int ldo, int mode)
{
    __shared__ float sb[32];
    int row = blockIdx.x, tid = threadIdx.x;
    float x0 = in[(size_t)row * DD + tid];
    float x1 = in[(size_t)row * DD + 256 + tid];
    if (mode == 1) { x0 = tanh_bulk(x0); x1 = tanh_bulk(x1); }
    float s  = block_red_sum(x0 + x1, sb);
    float sq = block_red_sum(x0 * x0 + x1 * x1, sb);
    float mean = s * (1.f / 512.f);
    float var  = sq * (1.f / 512.f) - mean * mean;
    float rstd = rsqrtf(var + 1e-5f);
    float y0 = (x0 - mean) * rstd * gg[tid] + bb[tid];
    float y1 = (x1 - mean) * rstd * gg[256 + tid] + bb[256 + tid];
    if (mode == 0) { y0 = tanh_bulk(y0); y1 = tanh_bulk(y1); }
    out[(size_t)row * ldo + tid] = y0;
    out[(size_t)row * ldo + 256 + tid] = y1;
}

__global__ void rownorm_kernel(const float* __restrict__ src) {
    __shared__ float sb[32];
    int row = blockIdx.x, tid = threadIdx.x;
    float x0 = src[(size_t)row * DD + tid];
    float x1 = src[(size_t)row * DD + 256 + tid];
    float ss = block_red_sum(x0 * x0 + x1 * x1, sb);
    float inv = 1.f / fmaxf(sqrtf(ss), 1e-12f);
    g_sw[(size_t)row * DD + tid] = x0 * inv;
    g_sw[(size_t)row * DD + 256 + tid] = x1 * inv;
}

// ---------------- host ----------------
static inline void gemm(const float* A, const float* B, const float* bias, float* C,
                        int M, int N, int K, int lda, int ldb, int ldc,
                        float scale, int batch, long long sA, long long sB, long long sC,
                        int mt, bool tb, bool causal, int klim = 0, int elu_cols = 0)
{
    dim3 grid(N / 64, M / mt, batch);
    if (mt == 128) {
        if (tb) {
            if (causal) gemm_kernel<128, true, true><<<grid, 256>>>(A, B, bias, C, M, N, K, lda, ldb, ldc, sA, sB, sC, scale, klim, elu_cols);
            else        gemm_kernel<128, true, false><<<grid, 256>>>(A, B, bias, C, M, N, K, lda, ldb, ldc, sA, sB, sC, scale, klim, elu_cols);
        } else {
            gemm_kernel<128, false, false><<<grid, 256>>>(A, B, bias, C, M, N, K, lda, ldb, ldc, sA, sB, sC, scale, klim, elu_cols);
        }
    } else {
        if (tb) {
            if (causal) gemm_kernel<64, true, true><<<grid, 256>>>(A, B, bias, C, M, N, K, lda, ldb, ldc, sA, sB, sC, scale, klim, elu_cols);
            else        gemm_kernel<64, true, false><<<grid, 256>>>(A, B, bias, C, M, N, K, lda, ldb, ldc, sA, sB, sC, scale, klim, elu_cols);
        } else {
            gemm_kernel<64, false, false><<<grid, 256>>>(A, B, bias, C, M, N, K, lda, ldb, ldc, sA, sB, sC, scale, klim, elu_cols);
        }
    }
}

extern "C" void kernel_launch(void* const* d_in, const int* in_sizes, int n_in,
                              void* d_out, int out_size)
{
    (void)in_sizes; (void)n_in; (void)out_size;
    const int*   x        = (const int*)d_in[0];
    const float* h_f      = (const float*)d_in[1];
    const float* h_s      = (const float*)d_in[2];
    const float* soma_w   = (const float*)d_in[3];
    const float* fast_wih = (const float*)d_in[4];
    const float* fast_whh = (const float*)d_in[5];
    const float* fast_bih = (const float*)d_in[6];
    const float* fast_bhh = (const float*)d_in[7];
    const float* slow_wih = (const float*)d_in[8];
    const float* slow_whh = (const float*)d_in[9];
    const float* slow_bih = (const float*)d_in[10];
    const float* slow_bhh = (const float*)d_in[11];
    const float* qkv_w    = (const float*)d_in[12];
    const float* qkv_b    = (const float*)d_in[13];
    const float* gate_w   = (const float*)d_in[14];
    const float* gate_b   = (const float*)d_in[15];
    const float* gate_g   = (const float*)d_in[16];
    const float* gate_bb  = (const float*)d_in[17];
    const float* mem_bank = (const float*)d_in[18];
    const float* hip_qw   = (const float*)d_in[19];
    const float* hip_qb   = (const float*)d_in[20];
    const float* axon_w   = (const float*)d_in[21];
    const float* axon_b   = (const float*)d_in[22];
    const float* norm_g   = (const float*)d_in[23];
    const float* norm_b   = (const float*)d_in[24];

    float* out = (float*)d_out;
    float* out_logits  = out;            // [B,T,V]
    float* out_thought = out + 262144;   // [B,T,D]
    float* out_hf      = out + 786432;   // [1,B,D]
    float* out_hs      = out + 787456;   // [1,B,D]

    float *p_table, *p_pf, *p_ps, *p_qkv, *p_S, *p_attn, *p_comb,
          *p_tpre, *p_gatepre, *p_qh, *p_sw;
    cudaGetSymbolAddress((void**)&p_table,   g_table);
    cudaGetSymbolAddress((void**)&p_pf,      g_pf);
    cudaGetSymbolAddress((void**)&p_ps,      g_ps);
    cudaGetSymbolAddress((void**)&p_qkv,     g_qkv);
    cudaGetSymbolAddress((void**)&p_S,       g_S);
    cudaGetSymbolAddress((void**)&p_attn,    g_attn);
    cudaGetSymbolAddress((void**)&p_comb,    g_comb);
    cudaGetSymbolAddress((void**)&p_tpre,    g_tpre);
    cudaGetSymbolAddress((void**)&p_gatepre, g_gatepre);
    cudaGetSymbolAddress((void**)&p_qh,      g_qh);
    cudaGetSymbolAddress((void**)&p_sw,      g_sw);

    // normalized embedding rows for logits
    rownorm_kernel<<<VV, 256>>>(soma_w);

    // fast-GRU input-gate token table (M=256 -> MT64, 96 blocks)
    gemm(soma_w, fast_wih, fast_bih, p_table, 256, 1536, 512, 512, 512, 1536,
         1.f, 1, 0, 0, 0, 64, true, false);

    // reset counters BEFORE the GRU (keeps fused_gru in the ncu window)
    reset_bar_kernel<<<1, 1>>>();

    // batch-split fused GRUs -> p_f, comb[:,0:512], p_s, hf1, hs1
    fused_gru_kernel<<<2 * DOM_BLOCKS, GRU_THREADS>>>(
        fast_whh, fast_bhh, slow_wih, slow_bih, slow_whh, slow_bhh,
        p_table, x, h_f, h_s, p_pf, p_comb, p_ps, out_hf, out_hs);

    // projections from p_s
    gemm(p_ps, qkv_w,  qkv_b,  p_qkv,     1024, 1536, 512, 512, 512, 1536, 1.f, 1, 0, 0, 0, 128, true, false, 0, 1024);
    gemm(p_ps, gate_w, gate_b, p_gatepre, 1024,  512, 512, 512, 512,  512, 1.f, 1, 0, 0, 0, 64, true, false);
    gemm(p_ps, hip_qw, hip_qb, p_qh,      1024,  256 + 256, 512, 512, 512, 512, 1.f, 1, 0, 0, 0, 64, true, false);

    // linear attention == causal attention: S = q k^T (MT64 causal, finer culling)
    gemm(p_qkv, p_qkv + 512, nullptr, p_S, 512, 512, 512, 1536, 1536, 512,
         1.f, 2, 512LL * 1536, 512LL * 1536, 512LL * 512, 64, true, true);
    // num = S @ v (MT64, K capped at m0+64)
    gemm(p_S, p_qkv + 1024, nullptr, p_comb + 1024, 512, 512, 512, 512, 1536, 2048,
         1.f, 2, 512LL * 512, 512LL * 1536, 512LL * 2048, 64, false, false, 1, 0);
    den_div_kernel<<<BT, 256>>>();

    // intent = tanh(LN(gatepre)) -> combined[:, 512:1024]
    ln_kernel<<<BT, 256>>>(p_gatepre, gate_g, gate_bb, p_comb + 512, 2048, 0);

    // hippocampus: attn = softmax(qh @ mem^T / sqrt(D)); episodes = attn @ mem
    gemm(p_qh, mem_bank, nullptr, p_attn, 1024, 256, 512, 512, 512, 256,
         0.044194173824159216f, 1, 0, 0, 0, 64, true, false);
    softmax_kernel<<<BT, 256>>>();
    gemm(p_attn, mem_bank, nullptr, p_comb + 1536, 1024, 512, 256, 256, 512, 2048,
         1.f, 1, 0, 0, 0, 64, false, false);

    // thought = LN(tanh(combined @ axon_w^T + axon_b))  (K=2048 -> MT64, 128 blocks)
    gemm(p_comb, axon_w, axon_b, p_tpre, 1024, 512, 2048, 2048, 2048, 512,
         1.f, 1, 0, 0, 0, 64, true, false);
    ln_kernel<<<BT, 256>>>(p_tpre, norm_g, norm_b, out_thought, 512, 1);

    // logits = (thought @ sw^T) * 16
    gemm(out_thought, p_sw, nullptr, out_logits, 1024, 256, 512, 512, 512, 256,
         16.f, 1, 0, 0, 0, 64, true, false);
}

// round 16
// speedup vs baseline: 1.3740x; 1.0033x over previous
#include <cuda_runtime.h>
#include <math.h>

#define TT 512
#define DD 512
#define NBATCH 2
#define VV 256
#define MMEM 256
#define BT 1024
#define D3 1536
#define DOM_BLOCKS 64
#define UNITS 8
#define GRU_THREADS 384

// ---------------- static device scratch ----------------
__device__ float g_table[VV * D3];
__device__ float g_pf[BT * DD];
__device__ float g_ps[BT * DD];
__device__ float g_qkv[BT * D3];
__device__ float g_S[NBATCH * TT * TT];
__device__ float g_attn[BT * MMEM];
__device__ float g_comb[BT * 2048];
__device__ float g_tpre[BT * DD];
__device__ float g_gatepre[BT * DD];
__device__ float g_qh[BT * DD];
__device__ float g_wnorm[VV];               // 16 / ||soma_w_row||
__device__ float g_hf3[3][NBATCH * DD];
__device__ float g_hs3[3][NBATCH * DD];
__device__ unsigned g_barb[2][32];

// ---------------- block reductions ----------------
__device__ __forceinline__ float block_red_sum(float v, float* sb) {
    __syncthreads();
    int lane = threadIdx.x & 31, w = threadIdx.x >> 5;
    #pragma unroll
    for (int o = 16; o; o >>= 1) v += __shfl_xor_sync(0xffffffffu, v, o);
    if (lane == 0) sb[w] = v;
    __syncthreads();
    float r = (lane < (int)(blockDim.x >> 5)) ? sb[lane] : 0.f;
    #pragma unroll
    for (int o = 16; o; o >>= 1) r += __shfl_xor_sync(0xffffffffu, r, o);
    return r;
}

__device__ __forceinline__ float block_red_max(float v, float* sb) {
    __syncthreads();
    int lane = threadIdx.x & 31, w = threadIdx.x >> 5;
    #pragma unroll
    for (int o = 16; o; o >>= 1) v = fmaxf(v, __shfl_xor_sync(0xffffffffu, v, o));
    if (lane == 0) sb[w] = v;
    __syncthreads();
    float r = (lane < (int)(blockDim.x >> 5)) ? sb[lane] : -3.4e38f;
    #pragma unroll
    for (int o = 16; o; o >>= 1) r = fmaxf(r, __shfl_xor_sync(0xffffffffu, r, o));
    return r;
}

__global__ void reset_bar_kernel() { g_barb[0][0] = 0u; g_barb[1][0] = 0u; }

// ---------------- fast activations ----------------
__device__ __forceinline__ float sigf(float x) {
    return __fdividef(1.f, 1.f + __expf(-x));
}
__device__ __forceinline__ float tanhf_fast(float x) {
    float ax = fabsf(x);
    float t = __expf(-2.f * ax);
    float r = __fdividef(1.f - t, 1.f + t);
    return copysignf(r, x);
}

#define FMA2(d, a, b, c) \
    asm("fma.rn.f32x2 %0, %1, %2, %3;" : "=l"(d) : "l"(a), "l"(b), "l"(c))

// ---------------- batch-split fused GRU (R15 proven) ----------------
__global__ void __launch_bounds__(GRU_THREADS) fused_gru_kernel(
    const float* __restrict__ fast_whh, const float* __restrict__ fast_bhh,
    const float* __restrict__ slow_wih, const float* __restrict__ slow_bih,
    const float* __restrict__ slow_whh, const float* __restrict__ slow_bhh,
    const float* __restrict__ gi_table, const int* __restrict__ toks,
    const float* __restrict__ hf0, const float* __restrict__ hs0,
    float* __restrict__ pf, float* __restrict__ comb, float* __restrict__ ps,
    float* __restrict__ hfT, float* __restrict__ hsT)
{
    __shared__ float sg[3][3][UNITS];
    const int tid = threadIdx.x;
    const int w = tid >> 5, lane = tid & 31;
    const int dom = blockIdx.x >> 6;
    const int blk = blockIdx.x & 63;
    const int ibase = blk * UNITS;
    const int tr = w >> 2, up = w & 3;
    unsigned* barp = &g_barb[dom][0];

    const float* Wsrc = (tr == 0) ? fast_whh : ((tr == 1) ? slow_wih : slow_whh);
    ulonglong2 wreg[2][3][4];
    #pragma unroll
    for (int uu = 0; uu < 2; uu++) {
        const int u = ibase + up * 2 + uu;
        #pragma unroll
        for (int g = 0; g < 3; g++)
            #pragma unroll
            for (int j = 0; j < 4; j++)
                wreg[uu][g][j] = *(const ulonglong2*)&Wsrc[(size_t)(g * DD + u) * DD + lane * 4 + j * 128];
    }

    const int ci = ibase + lane;
    float b_r = 0.f, b_z = 0.f, b_n = 0.f;
    float b2_r = 0.f, b2_z = 0.f, b2_n = 0.f;
    float hprev = 0.f;
    if (w == 0 && lane < 8) {
        b_r = fast_bhh[ci]; b_z = fast_bhh[DD + ci]; b_n = fast_bhh[2 * DD + ci];
        hprev = hf0[dom * DD + ci];
        g_hf3[0][dom * DD + ci] = hprev;
    }
    if (w == 1 && lane < 8) {
        b_r = slow_bih[ci]; b_z = slow_bih[DD + ci]; b_n = slow_bih[2 * DD + ci];
        b2_r = slow_bhh[ci]; b2_z = slow_bhh[DD + ci]; b2_n = slow_bhh[2 * DD + ci];
        hprev = hs0[dom * DD + ci];
        g_hs3[0][dom * DD + ci] = hprev;
    }
    __syncthreads();
    if (tid == 0) {
        asm volatile("red.release.gpu.global.add.u32 [%0], 1;" :: "l"(barp) : "memory");
        unsigned v;
        do {
            asm volatile("ld.acquire.gpu.u32 %0, [%1];" : "=r"(v) : "l"(barp) : "memory");
        } while (v < DOM_BLOCKS);
    }
    __syncthreads();

    for (int t = 0; t <= TT; t++) {
        const int cur = t % 3, nxt = (t + 1) % 3;
        const int cur_s = (t + 2) % 3, nxt_s = t % 3;

        float gr = 0.f, gz = 0.f, gn = 0.f;
        if (w == 0 && lane < 8 && t < TT) {
            const int row = dom * TT + t;
            const float* gi = gi_table + (size_t)__ldg(&toks[row]) * D3;
            gr = __ldg(gi + ci); gz = __ldg(gi + DD + ci); gn = __ldg(gi + 2 * DD + ci);
        }

        const float* base;
        if (tr == 0)      base = &g_hf3[cur][dom * DD];
        else if (tr == 1) base = pf + (size_t)(dom * TT + ((t > 0) ? t - 1 : 0)) * DD;
        else              base = &g_hs3[cur_s][dom * DD];
        ulonglong2 xv[4];
        #pragma unroll
        for (int j = 0; j < 4; j++)
            xv[j] = __ldcg((const ulonglong2*)(base + lane * 4 + j * 128));

        unsigned long long acc2[2][3];
        #pragma unroll
        for (int uu = 0; uu < 2; uu++)
            #pragma unroll
            for (int g = 0; g < 3; g++) acc2[uu][g] = 0ull;
        #pragma unroll
        for (int j = 0; j < 4; j++)
            #pragma unroll
            for (int uu = 0; uu < 2; uu++)
                #pragma unroll
                for (int g = 0; g < 3; g++) {
                    FMA2(acc2[uu][g], wreg[uu][g][j].x, xv[j].x, acc2[uu][g]);
                    FMA2(acc2[uu][g], wreg[uu][g][j].y, xv[j].y, acc2[uu][g]);
                }

        float a[2][3];
        #pragma unroll
        for (int uu = 0; uu < 2; uu++)
            #pragma unroll
            for (int g = 0; g < 3; g++) {
                float lo, hi;
                asm("mov.b64 {%0, %1}, %2;" : "=f"(lo), "=f"(hi) : "l"(acc2[uu][g]));
                a[uu][g] = lo + hi;
            }
        #pragma unroll
        for (int o = 16; o; o >>= 1)
            #pragma unroll
            for (int uu = 0; uu < 2; uu++)
                #pragma unroll
                for (int g = 0; g < 3; g++)
                    a[uu][g] += __shfl_xor_sync(0xffffffffu, a[uu][g], o);

        if (lane == 0) {
            #pragma unroll
            for (int uu = 0; uu < 2; uu++)
                #pragma unroll
                for (int g = 0; g < 3; g++)
                    sg[tr][g][up * 2 + uu] = a[uu][g];
        }
        __syncthreads();

        if (w == 0 && lane < 8 && t < TT) {
            const int row = dom * TT + t;
            float r = sigf(gr + sg[0][0][lane] + b_r);
            float z = sigf(gz + sg[0][1][lane] + b_z);
            float n = tanhf_fast(gn + r * (sg[0][2][lane] + b_n));
            float hnew = (1.f - z) * n + z * hprev;
            hprev = hnew;
            g_hf3[nxt][dom * DD + ci] = hnew;
            pf[(size_t)row * DD + ci] = hnew;
            comb[(size_t)row * 2048 + ci] = hnew;
            if (t == TT - 1) hfT[dom * DD + ci] = hnew;
        }
        if (w == 1 && lane < 8 && t >= 1) {
            const int ts = t - 1, row = dom * TT + ts;
            float r = sigf(sg[1][0][lane] + b_r + sg[2][0][lane] + b2_r);
            float z = sigf(sg[1][1][lane] + b_z + sg[2][1][lane] + b2_z);
            float n = tanhf_fast(sg[1][2][lane] + b_n + r * (sg[2][2][lane] + b2_n));
            float hnew = (1.f - z) * n + z * hprev;
            hprev = hnew;
            g_hs3[nxt_s][dom * DD + ci] = hnew;
            ps[(size_t)row * DD + ci] = hnew;
            if (ts == TT - 1) hsT[dom * DD + ci] = hnew;
        }
        if (t < TT) {
            __syncthreads();
            if (tid == 0) {
                asm volatile("red.release.gpu.global.add.u32 [%0], 1;" :: "l"(barp) : "memory");
                unsigned target = (unsigned)(t + 2) * DOM_BLOCKS;
                unsigned v;
                do {
                    asm volatile("ld.acquire.gpu.u32 %0, [%1];" : "=r"(v) : "l"(barp) : "memory");
                } while (v < target);
            }
            __syncthreads();
        }
    }
}

// ---------------- GEMM: MT x 64 tile, 256 thr, f32x2 FMA ----------------
// TB: Bm stored [N,K]; else [K,N]. CAUSAL: tile-cull + mask. klim: Kc=m0+MT.
// elu_cols: elu+1 on cols < elu_cols. colscale: per-output-column multiplier.
// sBias: per-z bias offset (for batched multi-weight launches).
template <int MT, bool TB, bool CAUSAL>
__global__ void __launch_bounds__(256) gemm_kernel(
    const float* __restrict__ A, const float* __restrict__ Bm,
    const float* __restrict__ bias, float* __restrict__ C,
    int M, int N, int K, int lda, int ldb, int ldc,
    long long sA, long long sB, long long sC, long long sBias,
    float scale, int klim, int elu_cols, const float* __restrict__ colscale)
{
    constexpr int RP = MT / 32;
    __shared__ __align__(16) float As[2][16][MT + 4];
    __shared__ __align__(16) float Bs[2][16][68];
    const int z = blockIdx.z;
    A += (size_t)z * sA; Bm += (size_t)z * sB; C += (size_t)z * sC;
    if (bias) bias += (size_t)z * sBias;
    const int m0 = blockIdx.y * MT, n0 = blockIdx.x * 64;
    const int tid = threadIdx.x;
    const int ty = tid >> 4, tx = tid & 15;
    const int nn = n0 + (tx << 2);

    if (CAUSAL && n0 > m0 + MT - 1) {
        float4 zv = make_float4(0.f, 0.f, 0.f, 0.f);
        #pragma unroll
        for (int p2 = 0; p2 < RP; p2++)
            #pragma unroll
            for (int half = 0; half < 2; half++) {
                const int mm = m0 + ty * 2 * RP + (p2 << 1) + half;
                *(float4*)(C + (size_t)mm * ldc + nn) = zv;
            }
        return;
    }

    const int Kc = klim ? ((m0 + MT < K) ? m0 + MT : K) : K;
    const int ar = tid >> 2, ac = (tid & 3) << 2;
    const int bk = tid >> 4, bn = (tid & 15) << 2;

    float4 a0 = *(const float4*)(A + (size_t)(m0 + ar) * lda + ac);
    float4 a1;
    if (MT == 128) a1 = *(const float4*)(A + (size_t)(m0 + ar + 64) * lda + ac);
    float4 bv;
    if (TB) bv = *(const float4*)(Bm + (size_t)(n0 + ar) * ldb + ac);
    else    bv = *(const float4*)(Bm + (size_t)bk * ldb + n0 + bn);

    {
        As[0][ac + 0][ar] = a0.x; As[0][ac + 1][ar] = a0.y;
        As[0][ac + 2][ar] = a0.z; As[0][ac + 3][ar] = a0.w;
        if (MT == 128) {
            As[0][ac + 0][ar + 64] = a1.x; As[0][ac + 1][ar + 64] = a1.y;
            As[0][ac + 2][ar + 64] = a1.z; As[0][ac + 3][ar + 64] = a1.w;
        }
        if (TB) {
            Bs[0][ac + 0][ar] = bv.x; Bs[0][ac + 1][ar] = bv.y;
            Bs[0][ac + 2][ar] = bv.z; Bs[0][ac + 3][ar] = bv.w;
        } else {
            *(float4*)&Bs[0][bk][bn] = bv;
        }
    }
    __syncthreads();

    unsigned long long acc[RP][4];
    #pragma unroll
    for (int p2 = 0; p2 < RP; p2++)
        #pragma unroll
        for (int jj = 0; jj < 4; jj++) acc[p2][jj] = 0ull;

    const int P = Kc >> 4;
    int buf = 0;
    for (int p = 0; p < P; p++) {
        if (p + 1 < P) {
            const int k0n = (p + 1) << 4;
            a0 = *(const float4*)(A + (size_t)(m0 + ar) * lda + k0n + ac);
            if (MT == 128) a1 = *(const float4*)(A + (size_t)(m0 + ar + 64) * lda + k0n + ac);
            if (TB) bv = *(const float4*)(Bm + (size_t)(n0 + ar) * ldb + k0n + ac);
            else    bv = *(const float4*)(Bm + (size_t)(k0n + bk) * ldb + n0 + bn);
        }
        #pragma unroll
        for (int k = 0; k < 16; k++) {
            ulonglong2 af[RP / 2];
            af[0] = *(const ulonglong2*)&As[buf][k][ty * 2 * RP];
            if (RP == 4) af[1] = *(const ulonglong2*)&As[buf][k][ty * 2 * RP + 4];
            float4 b4 = *(const float4*)&Bs[buf][k][tx << 2];
            unsigned long long bd[4];
            asm("mov.b64 %0, {%1, %1};" : "=l"(bd[0]) : "f"(b4.x));
            asm("mov.b64 %0, {%1, %1};" : "=l"(bd[1]) : "f"(b4.y));
            asm("mov.b64 %0, {%1, %1};" : "=l"(bd[2]) : "f"(b4.z));
            asm("mov.b64 %0, {%1, %1};" : "=l"(bd[3]) : "f"(b4.w));
            #pragma unroll
            for (int p2 = 0; p2 < RP; p2++) {
                unsigned long long av = (p2 & 1) ? af[p2 >> 1].y : af[p2 >> 1].x;
                #pragma unroll
                for (int jj = 0; jj < 4; jj++)
                    FMA2(acc[p2][jj], av, bd[jj], acc[p2][jj]);
            }
        }
        if (p + 1 < P) {
            const int nb = buf ^ 1;
            As[nb][ac + 0][ar] = a0.x; As[nb][ac + 1][ar] = a0.y;
            As[nb][ac + 2][ar] = a0.z; As[nb][ac + 3][ar] = a0.w;
            if (MT == 128) {
                As[nb][ac + 0][ar + 64] = a1.x; As[nb][ac + 1][ar + 64] = a1.y;
                As[nb][ac + 2][ar + 64] = a1.z; As[nb][ac + 3][ar + 64] = a1.w;
            }
            if (TB) {
                Bs[nb][ac + 0][ar] = bv.x; Bs[nb][ac + 1][ar] = bv.y;
                Bs[nb][ac + 2][ar] = bv.z; Bs[nb][ac + 3][ar] = bv.w;
            } else {
                *(float4*)&Bs[nb][bk][bn] = bv;
            }
            __syncthreads();
            buf = nb;
        }
    }

    float4 bvec;
    if (bias) bvec = *(const float4*)&bias[nn];
    float4 csv;
    if (colscale) csv = *(const float4*)&colscale[nn];
    #pragma unroll
    for (int p2 = 0; p2 < RP; p2++) {
        float rlo[4], rhi[4];
        #pragma unroll
        for (int jj = 0; jj < 4; jj++) {
            float lo, hi;
            asm("mov.b64 {%0, %1}, %2;" : "=f"(lo), "=f"(hi) : "l"(acc[p2][jj]));
            rlo[jj] = lo; rhi[jj] = hi;
        }
        #pragma unroll
        for (int half = 0; half < 2; half++) {
            const int mm = m0 + ty * 2 * RP + (p2 << 1) + half;
            float* rr = half ? rhi : rlo;
            float4 cv;
            cv.x = rr[0] * scale; cv.y = rr[1] * scale;
            cv.z = rr[2] * scale; cv.w = rr[3] * scale;
            if (colscale) { cv.x *= csv.x; cv.y *= csv.y; cv.z *= csv.z; cv.w *= csv.w; }
            if (bias) { cv.x += bvec.x; cv.y += bvec.y; cv.z += bvec.z; cv.w += bvec.w; }
            if (elu_cols) {
                if (nn + 0 < elu_cols) cv.x = cv.x > 0.f ? cv.x + 1.f : __expf(cv.x);
                if (nn + 1 < elu_cols) cv.y = cv.y > 0.f ? cv.y + 1.f : __expf(cv.y);
                if (nn + 2 < elu_cols) cv.z = cv.z > 0.f ? cv.z + 1.f : __expf(cv.z);
                if (nn + 3 < elu_cols) cv.w = cv.w > 0.f ? cv.w + 1.f : __expf(cv.w);
            }
            if (CAUSAL) {
                if (nn + 0 > mm) cv.x = 0.f;
                if (nn + 1 > mm) cv.y = 0.f;
                if (nn + 2 > mm) cv.z = 0.f;
                if (nn + 3 > mm) cv.w = 0.f;
            }
            *(float4*)(C + (size_t)mm * ldc + nn) = cv;
        }
    }
}

// ---------------- small kernels ----------------
__global__ void den_div_kernel() {
    __shared__ float sb[32];
    int row = blockIdx.x;
    float s = 0.f;
    for (int c = threadIdx.x; c < TT; c += 256) s += g_S[(size_t)row * TT + c];
    s = block_red_sum(s, sb);
    float inv = __fdividef(1.f, s + 1e-6f);
    for (int j = threadIdx.x; j < DD; j += 256)
        g_comb[(size_t)row * 2048 + 1024 + j] *= inv;
}

__global__ void softmax_kernel() {
    __shared__ float sb[32];
    int row = blockIdx.x;
    float x = g_attn[(size_t)row * MMEM + threadIdx.x];
    float m = block_red_max(x, sb);
    float e = __expf(x - m);
    float s = block_red_sum(e, sb);
    g_attn[(size_t)row * MMEM + threadIdx.x] = e / s;
}

__device__ __forceinline__ float tanh_bulk(float x) {
    float ax = fabsf(x);
    float t = __expf(-2.f * ax);
    float r = __fdividef(1.f - t, 1.f + t);
    return copysignf(r, x);
}

// mode 0: out = tanh(LN(in));  mode 1: out = LN(tanh(in))
__global__ void ln_kernel(const float* __restrict__ in, const float* __restrict__ gg,
                          const float* __restrict__ bb, float* __restrict__ out,
                          int ldo, int mode)
{
    __shared__ float sb[32];
    int row = blockIdx.x, tid = threadIdx.x;
    float x0 = in[(size_t)row * DD + tid];
    float x1 = in[(size_t)row * DD + 256 + tid];
    if (mode == 1) { x0 = tanh_bulk(x0); x1 = tanh_bulk(x1); }
    float s  = block_red_sum(x0 + x1, sb);
    float sq = block_red_sum(x0 * x0 + x1 * x1, sb);
    float mean = s * (1.f / 512.f);
    float var  = sq * (1.f / 512.f) - mean * mean;
    float rstd = rsqrtf(var + 1e-5f);
    float y0 = (x0 - mean) * rstd * gg[tid] + bb[tid];
    float y1 = (x1 - mean) * rstd * gg[256 + tid] + bb[256 + tid];
    if (mode == 0) { y0 = tanh_bulk(y0); y1 = tanh_bulk(y1); }
    out[(size_t)row * ldo + tid] = y0;
    out[(size_t)row * ldo + 256 + tid] = y1;
}

// g_wnorm[row] = 16 / max(||soma_w[row]||, 1e-12)
__global__ void rownorm_kernel(const float* __restrict__ src) {
    __shared__ float sb[32];
    int row = blockIdx.x, tid = threadIdx.x;
    float x0 = src[(size_t)row * DD + tid];
    float x1 = src[(size_t)row * DD + 256 + tid];
    float ss = block_red_sum(x0 * x0 + x1 * x1, sb);
    if (tid == 0) g_wnorm[row] = 16.f / fmaxf(sqrtf(ss), 1e-12f);
}

// ---------------- host ----------------
static inline void gemm(const float* A, const float* B, const float* bias, float* C,
                        int M, int N, int K, int lda, int ldb, int ldc,
                        float scale, int batch, long long sA, long long sB, long long sC,
                        int mt, bool tb, bool causal, int klim = 0, int elu_cols = 0,
                        long long sBias = 0, const float* colscale = nullptr)
{
    dim3 grid(N / 64, M / mt, batch);
    if (mt == 128) {
        if (tb) {
            if (causal) gemm_kernel<128, true, true><<<grid, 256>>>(A, B, bias, C, M, N, K, lda, ldb, ldc, sA, sB, sC, sBias, scale, klim, elu_cols, colscale);
            else        gemm_kernel<128, true, false><<<grid, 256>>>(A, B, bias, C, M, N, K, lda, ldb, ldc, sA, sB, sC, sBias, scale, klim, elu_cols, colscale);
        } else {
            gemm_kernel<128, false, false><<<grid, 256>>>(A, B, bias, C, M, N, K, lda, ldb, ldc, sA, sB, sC, sBias, scale, klim, elu_cols, colscale);
        }
    } else {
        if (tb) {
            if (causal) gemm_kernel<64, true, true><<<grid, 256>>>(A, B, bias, C, M, N, K, lda, ldb, ldc, sA, sB, sC, sBias, scale, klim, elu_cols, colscale);
            else        gemm_kernel<64, true, false><<<grid, 256>>>(A, B, bias, C, M, N, K, lda, ldb, ldc, sA, sB, sC, sBias, scale, klim, elu_cols, colscale);
        } else {
            gemm_kernel<64, false, false><<<grid, 256>>>(A, B, bias, C, M, N, K, lda, ldb, ldc, sA, sB, sC, sBias, scale, klim, elu_cols, colscale);
        }
    }
}

extern "C" void kernel_launch(void* const* d_in, const int* in_sizes, int n_in,
                              void* d_out, int out_size)
{
    (void)in_sizes; (void)n_in; (void)out_size;
    const int*   x        = (const int*)d_in[0];
    const float* h_f      = (const float*)d_in[1];
    const float* h_s      = (const float*)d_in[2];
    const float* soma_w   = (const float*)d_in[3];
    const float* fast_wih = (const float*)d_in[4];
    const float* fast_whh = (const float*)d_in[5];
    const float* fast_bih = (const float*)d_in[6];
    const float* fast_bhh = (const float*)d_in[7];
    const float* slow_wih = (const float*)d_in[8];
    const float* slow_whh = (const float*)d_in[9];
    const float* slow_bih = (const float*)d_in[10];
    const float* slow_bhh = (const float*)d_in[11];
    const float* qkv_w    = (const float*)d_in[12];
    const float* qkv_b    = (const float*)d_in[13];
    const float* gate_w   = (const float*)d_in[14];
    const float* gate_b   = (const float*)d_in[15];
    const float* gate_g   = (const float*)d_in[16];
    const float* gate_bb  = (const float*)d_in[17];
    const float* mem_bank = (const float*)d_in[18];
    const float* hip_qw   = (const float*)d_in[19];
    const float* hip_qb   = (const float*)d_in[20];
    const float* axon_w   = (const float*)d_in[21];
    const float* axon_b   = (const float*)d_in[22];
    const float* norm_g   = (const float*)d_in[23];
    const float* norm_b   = (const float*)d_in[24];

    float* out = (float*)d_out;
    float* out_logits  = out;            // [B,T,V]
    float* out_thought = out + 262144;   // [B,T,D]
    float* out_hf      = out + 786432;   // [1,B,D]
    float* out_hs      = out + 787456;   // [1,B,D]

    float *p_table, *p_pf, *p_ps, *p_qkv, *p_S, *p_attn, *p_comb,
          *p_tpre, *p_gatepre, *p_qh, *p_wnorm;
    cudaGetSymbolAddress((void**)&p_table,   g_table);
    cudaGetSymbolAddress((void**)&p_pf,      g_pf);
    cudaGetSymbolAddress((void**)&p_ps,      g_ps);
    cudaGetSymbolAddress((void**)&p_qkv,     g_qkv);
    cudaGetSymbolAddress((void**)&p_S,       g_S);
    cudaGetSymbolAddress((void**)&p_attn,    g_attn);
    cudaGetSymbolAddress((void**)&p_comb,    g_comb);
    cudaGetSymbolAddress((void**)&p_tpre,    g_tpre);
    cudaGetSymbolAddress((void**)&p_gatepre, g_gatepre);
    cudaGetSymbolAddress((void**)&p_qh,      g_qh);
    cudaGetSymbolAddress((void**)&p_wnorm,   g_wnorm);

    // per-row 16/||soma_w|| for the logits epilogue
    rownorm_kernel<<<VV, 256>>>(soma_w);

    // fast-GRU input-gate token table
    gemm(soma_w, fast_wih, fast_bih, p_table, 256, 1536, 512, 512, 512, 1536,
         1.f, 1, 0, 0, 0, 64, true, false);

    reset_bar_kernel<<<1, 1>>>();

    // batch-split fused GRUs -> p_f, comb[:,0:512], p_s, hf1, hs1
    fused_gru_kernel<<<2 * DOM_BLOCKS, GRU_THREADS>>>(
        fast_whh, fast_bhh, slow_wih, slow_bih, slow_whh, slow_bhh,
        p_table, x, h_f, h_s, p_pf, p_comb, p_ps, out_hf, out_hs);

    // qkv projection (elu fused for q,k cols), MT=64 for tighter waves
    gemm(p_ps, qkv_w, qkv_b, p_qkv, 1024, 1536, 512, 512, 512, 1536,
         1.f, 1, 0, 0, 0, 64, true, false, 0, 1024);

    // gate + hip projections merged into ONE batched launch (z=0: gate, z=1: hip)
    gemm(p_ps, gate_w, gate_b, p_gatepre, 1024, 512, 512, 512, 512, 512,
         1.f, 2, 0, (long long)(hip_qw - gate_w), (long long)(p_qh - p_gatepre),
         64, true, false, 0, 0, (long long)(hip_qb - gate_b));

    // linear attention == causal attention: S = q k^T (MT64 causal culling)
    gemm(p_qkv, p_qkv + 512, nullptr, p_S, 512, 512, 512, 1536, 1536, 512,
         1.f, 2, 512LL * 1536, 512LL * 1536, 512LL * 512, 64, true, true);
    // num = S @ v (K capped at m0+64)
    gemm(p_S, p_qkv + 1024, nullptr, p_comb + 1024, 512, 512, 512, 512, 1536, 2048,
         1.f, 2, 512LL * 512, 512LL * 1536, 512LL * 2048, 64, false, false, 1, 0);
    den_div_kernel<<<BT, 256>>>();

    // intent = tanh(LN(gatepre)) -> combined[:, 512:1024]
    ln_kernel<<<BT, 256>>>(p_gatepre, gate_g, gate_bb, p_comb + 512, 2048, 0);

    // hippocampus: attn = softmax(qh @ mem^T / sqrt(D)); episodes = attn @ mem
    gemm(p_qh, mem_bank, nullptr, p_attn, 1024, 256, 512, 512, 512, 256,
         0.044194173824159216f, 1, 0, 0, 0, 64, true, false);
    softmax_kernel<<<BT, 256>>>();
    gemm(p_attn, mem_bank, nullptr, p_comb + 1536, 1024, 512, 256, 256, 512, 2048,
         1.f, 1, 0, 0, 0, 64, false, false);

    // thought = LN(tanh(combined @ axon_w^T + axon_b))
    gemm(p_comb, axon_w, axon_b, p_tpre, 1024, 512, 2048, 2048, 2048, 512,
         1.f, 1, 0, 0, 0, 64, true, false);
    ln_kernel<<<BT, 256>>>(p_tpre, norm_g, norm_b, out_thought, 512, 1);

    // logits = (thought @ soma_w^T) * (16/||soma_w_row||)   (norm folded into epilogue)
    gemm(out_thought, soma_w, nullptr, out_logits, 1024, 256, 512, 512, 512, 256,
         1.f, 1, 0, 0, 0, 64, true, false, 0, 0, 0, p_wnorm);
}